// round 1
// baseline (speedup 1.0000x reference)
#include <cuda_runtime.h>
#include <math.h>

// ---------------- problem dims ----------------
#define B_    2
#define SQ_   1024
#define D_    2048
#define H_    16
#define HD_   128
#define SP_   1024
#define SS_   1024
#define SM_   512
#define SKV_  2560
#define DP_   1280
#define DS_   1024
#define DM_   768
#define INNER_ 8192

// ---------------- scratch (device globals; no allocations) ----------------
__device__ float g_qn [B_*SQ_*D_];
__device__ float g_q  [B_*SQ_*D_];
__device__ float g_kp [B_*SP_*D_];
__device__ float g_ks [B_*SS_*D_];
__device__ float g_km [B_*SM_*D_];
__device__ float g_vp [B_*SP_*D_];
__device__ float g_vs [B_*SS_*D_];
__device__ float g_vm [B_*SM_*D_];
__device__ float g_ctx[B_*SQ_*D_];
__device__ float g_h  [B_*SQ_*D_];
__device__ float g_ln [B_*SQ_*D_];
__device__ float g_ff [B_*SQ_*INNER_];

// ---------------- block reduce ----------------
__device__ __forceinline__ float blockReduceSum(float v) {
    __shared__ float sh[32];
    __syncthreads();
    int lane = threadIdx.x & 31, w = threadIdx.x >> 5;
    #pragma unroll
    for (int o = 16; o > 0; o >>= 1) v += __shfl_xor_sync(0xffffffffu, v, o);
    if (lane == 0) sh[w] = v;
    __syncthreads();
    float r = 0.f;
    if (threadIdx.x < (blockDim.x >> 5)) r = sh[threadIdx.x];
    if (w == 0) {
        #pragma unroll
        for (int o = 16; o > 0; o >>= 1) r += __shfl_xor_sync(0xffffffffu, r, o);
        if (lane == 0) sh[0] = r;
    }
    __syncthreads();
    return sh[0];
}

// ---------------- RMSNorm: y = x * rsqrt(mean(x^2)+1e-6) * w ----------------
__global__ __launch_bounds__(256) void rmsnorm_k(const float* __restrict__ x,
                                                 const float* __restrict__ w,
                                                 float* __restrict__ y) {
    int row = blockIdx.x;
    const float* xr = x + (size_t)row * D_;
    float ss = 0.f;
    for (int t = threadIdx.x; t < D_; t += 256) { float v = xr[t]; ss += v * v; }
    ss = blockReduceSum(ss);
    float inv = rsqrtf(ss / (float)D_ + 1e-6f);
    float* yr = y + (size_t)row * D_;
    for (int t = threadIdx.x; t < D_; t += 256) yr[t] = xr[t] * inv * w[t];
}

// ---------------- LayerNorm: (x-mu)*rsqrt(var+1e-5)*g + b ----------------
__global__ __launch_bounds__(256) void layernorm_k(const float* __restrict__ x,
                                                   const float* __restrict__ gg,
                                                   const float* __restrict__ bb,
                                                   float* __restrict__ y) {
    int row = blockIdx.x;
    const float* xr = x + (size_t)row * D_;
    float s = 0.f;
    for (int t = threadIdx.x; t < D_; t += 256) s += xr[t];
    s = blockReduceSum(s);
    float mu = s / (float)D_;
    float vs = 0.f;
    for (int t = threadIdx.x; t < D_; t += 256) { float d = xr[t] - mu; vs += d * d; }
    vs = blockReduceSum(vs);
    float inv = rsqrtf(vs / (float)D_ + 1e-5f);
    float* yr = y + (size_t)row * D_;
    for (int t = threadIdx.x; t < D_; t += 256)
        yr[t] = (xr[t] - mu) * inv * gg[t] + bb[t];
}

// ---------------- SGEMM 128x128x8, 8x8 microtile, fused epilogues ----------------
// EPI 0: C = (A*B + bias) * scale
// EPI 1: C = res + tanh(gate)*(A*B + bias)
// EPI 2: C = gelu_exact(A*B)
// EPI 3: C = res + tanh(gate)*(A*B)
template <int EPI>
__global__ __launch_bounds__(256) void sgemm(const float* __restrict__ A,
                                             const float* __restrict__ Bm,
                                             const float* __restrict__ bias,
                                             const float* __restrict__ res,
                                             const float* __restrict__ gate,
                                             float* __restrict__ C,
                                             int M, int N, int K, float scale) {
    __shared__ float As[8][128];
    __shared__ float Bs[8][132];
    const int tid = threadIdx.x;
    const int tx = tid & 15, ty = tid >> 4;
    const int row0 = blockIdx.y * 128, col0 = blockIdx.x * 128;

    const int a_r = tid >> 1;
    const int a_c = (tid & 1) << 2;
    const int b_r = tid >> 5;
    const int b_c = (tid & 31) << 2;

    const float* Ap = A + (size_t)(row0 + a_r) * K + a_c;
    const float* Bp = Bm + (size_t)b_r * N + col0 + b_c;

    float acc[8][8];
    #pragma unroll
    for (int i = 0; i < 8; i++)
        #pragma unroll
        for (int j = 0; j < 8; j++) acc[i][j] = 0.f;

    for (int k0 = 0; k0 < K; k0 += 8) {
        float4 av = *(const float4*)(Ap + k0);
        float4 bv = *(const float4*)(Bp + (size_t)k0 * N);
        As[a_c + 0][a_r] = av.x;
        As[a_c + 1][a_r] = av.y;
        As[a_c + 2][a_r] = av.z;
        As[a_c + 3][a_r] = av.w;
        *(float4*)&Bs[b_r][b_c] = bv;
        __syncthreads();
        #pragma unroll
        for (int kk = 0; kk < 8; kk++) {
            float ar[8], br[8];
            *(float4*)(ar)     = *(const float4*)&As[kk][ty * 8];
            *(float4*)(ar + 4) = *(const float4*)&As[kk][ty * 8 + 4];
            *(float4*)(br)     = *(const float4*)&Bs[kk][tx * 8];
            *(float4*)(br + 4) = *(const float4*)&Bs[kk][tx * 8 + 4];
            #pragma unroll
            for (int i = 0; i < 8; i++)
                #pragma unroll
                for (int j = 0; j < 8; j++) acc[i][j] += ar[i] * br[j];
        }
        __syncthreads();
    }

    float g = 0.f;
    if (EPI == 1 || EPI == 3) g = tanhf(gate[0]);

    #pragma unroll
    for (int i = 0; i < 8; i++) {
        int r = row0 + ty * 8 + i;
        #pragma unroll
        for (int j = 0; j < 8; j++) {
            int c = col0 + tx * 8 + j;
            float v = acc[i][j];
            if (EPI == 0) {
                v = (v + bias[c]) * scale;
            } else if (EPI == 1) {
                v = res[(size_t)r * N + c] + g * (v + bias[c]);
            } else if (EPI == 2) {
                v = 0.5f * v * (1.0f + erff(v * 0.70710678118654752f));
            } else {
                v = res[(size_t)r * N + c] + g * v;
            }
            C[(size_t)r * N + c] = v;
        }
    }
}

// ---------------- flash attention: BQ=64, BKV=64, HD=128 ----------------
// smem: Qs[64][132] | KVs[64][132] (K then V) | Ps[64][68]
#define ATTN_SMEM ((2 * 64 * 132 + 64 * 68) * 4)

__global__ __launch_bounds__(256) void attn_kernel(
    const float* __restrict__ q,
    const float* __restrict__ kp, const float* __restrict__ ksg, const float* __restrict__ kmg,
    const float* __restrict__ vp, const float* __restrict__ vsg, const float* __restrict__ vmg,
    const float* __restrict__ qmask, const float* __restrict__ pmask,
    const float* __restrict__ smask, const float* __restrict__ mmask,
    float* __restrict__ ctx) {
    extern __shared__ float smf[];
    float* Qs  = smf;                 // 64*132
    float* KVs = smf + 64 * 132;      // 64*132
    float* Ps  = smf + 2 * 64 * 132;  // 64*68

    const int qt = blockIdx.x;  // 0..15
    const int h  = blockIdx.y;  // 0..15
    const int b  = blockIdx.z;  // 0..1
    const int q0 = qt * 64;
    const int tid = threadIdx.x;
    const int tx = tid & 15, ty = tid >> 4;

    // load Q tile [64 x 128]
    const float* Qg = q + ((size_t)(b * SQ_ + q0)) * D_ + h * HD_;
    for (int t = tid; t < 64 * 32; t += 256) {
        int r = t >> 5, c4 = (t & 31);
        *(float4*)(Qs + r * 132 + c4 * 4) = *(const float4*)(Qg + (size_t)r * D_ + c4 * 4);
    }

    float m[4], l[4], acc[4][8];
    #pragma unroll
    for (int i = 0; i < 4; i++) {
        m[i] = -1e30f; l[i] = 0.f;
        #pragma unroll
        for (int j = 0; j < 8; j++) acc[i][j] = 0.f;
    }
    float qm[4];
    #pragma unroll
    for (int i = 0; i < 4; i++) qm[i] = qmask[b * SQ_ + q0 + ty * 4 + i];

    const float4* Q4 = (const float4*)Qs;
    const float4* K4 = (const float4*)KVs;

    for (int kv0 = 0; kv0 < SKV_; kv0 += 64) {
        const float *Kseg, *Vseg, *mseg;
        int sr;
        if (kv0 < SP_) {
            Kseg = kp + (size_t)b * SP_ * D_; Vseg = vp + (size_t)b * SP_ * D_;
            mseg = pmask + b * SP_; sr = kv0;
        } else if (kv0 < SP_ + SS_) {
            Kseg = ksg + (size_t)b * SS_ * D_; Vseg = vsg + (size_t)b * SS_ * D_;
            mseg = smask + b * SS_; sr = kv0 - SP_;
        } else {
            Kseg = kmg + (size_t)b * SM_ * D_; Vseg = vmg + (size_t)b * SM_ * D_;
            mseg = mmask + b * SM_; sr = kv0 - SP_ - SS_;
        }

        __syncthreads();  // prior P*V reads of KVs/Ps complete
        const float* Kg = Kseg + (size_t)sr * D_ + h * HD_;
        for (int t = tid; t < 64 * 32; t += 256) {
            int r = t >> 5, c4 = (t & 31);
            *(float4*)(KVs + r * 132 + c4 * 4) = *(const float4*)(Kg + (size_t)r * D_ + c4 * 4);
        }
        __syncthreads();

        // S[r][c] = sum_k Q[r][k]*K[c][k]; rows ty*4+i, cols tx+16*j
        float s[4][4];
        #pragma unroll
        for (int i = 0; i < 4; i++)
            #pragma unroll
            for (int j = 0; j < 4; j++) s[i][j] = 0.f;

        #pragma unroll 4
        for (int k4 = 0; k4 < 32; k4++) {
            float4 qv[4], kv[4];
            #pragma unroll
            for (int i = 0; i < 4; i++) qv[i] = Q4[(ty * 4 + i) * 33 + k4];
            #pragma unroll
            for (int j = 0; j < 4; j++) kv[j] = K4[(tx + 16 * j) * 33 + k4];
            #pragma unroll
            for (int i = 0; i < 4; i++)
                #pragma unroll
                for (int j = 0; j < 4; j++)
                    s[i][j] += qv[i].x * kv[j].x + qv[i].y * kv[j].y +
                               qv[i].z * kv[j].z + qv[i].w * kv[j].w;
        }

        // mask
        float kmv[4];
        #pragma unroll
        for (int j = 0; j < 4; j++) kmv[j] = mseg[sr + tx + 16 * j];
        #pragma unroll
        for (int i = 0; i < 4; i++)
            #pragma unroll
            for (int j = 0; j < 4; j++)
                if (qm[i] == 0.f || kmv[j] == 0.f) s[i][j] = -3.0e38f;

        // online softmax update
        #pragma unroll
        for (int i = 0; i < 4; i++) {
            float mx = fmaxf(fmaxf(s[i][0], s[i][1]), fmaxf(s[i][2], s[i][3]));
            #pragma unroll
            for (int o = 8; o > 0; o >>= 1)
                mx = fmaxf(mx, __shfl_xor_sync(0xffffffffu, mx, o, 16));
            float mn = fmaxf(m[i], mx);
            float alpha = expf(m[i] - mn);
            float ps = 0.f;
            #pragma unroll
            for (int j = 0; j < 4; j++) {
                float p = expf(s[i][j] - mn);
                Ps[(ty * 4 + i) * 68 + tx + 16 * j] = p;
                ps += p;
            }
            #pragma unroll
            for (int o = 8; o > 0; o >>= 1)
                ps += __shfl_xor_sync(0xffffffffu, ps, o, 16);
            l[i] = l[i] * alpha + ps;
            m[i] = mn;
            #pragma unroll
            for (int j = 0; j < 8; j++) acc[i][j] *= alpha;
        }
        __syncthreads();  // Ps complete; K no longer needed

        // load V tile into KVs
        const float* Vg = Vseg + (size_t)sr * D_ + h * HD_;
        for (int t = tid; t < 64 * 32; t += 256) {
            int r = t >> 5, c4 = (t & 31);
            *(float4*)(KVs + r * 132 + c4 * 4) = *(const float4*)(Vg + (size_t)r * D_ + c4 * 4);
        }
        __syncthreads();

        // O += P*V ; O rows ty*4+i, cols tx+16*j
        #pragma unroll 2
        for (int kk = 0; kk < 64; kk++) {
            float pv[4];
            #pragma unroll
            for (int i = 0; i < 4; i++) pv[i] = Ps[(ty * 4 + i) * 68 + kk];
            #pragma unroll
            for (int j = 0; j < 8; j++) {
                float vv = KVs[kk * 132 + tx + 16 * j];
                #pragma unroll
                for (int i = 0; i < 4; i++) acc[i][j] += pv[i] * vv;
            }
        }
    }

    // epilogue: O /= l ; write ctx[b, q, h*128 + c]
    float* Og = ctx + ((size_t)(b * SQ_ + q0)) * D_ + h * HD_;
    #pragma unroll
    for (int i = 0; i < 4; i++) {
        float inv = 1.0f / l[i];
        #pragma unroll
        for (int j = 0; j < 8; j++)
            Og[(size_t)(ty * 4 + i) * D_ + tx + 16 * j] = acc[i][j] * inv;
    }
}

// ---------------- launcher ----------------
extern "C" void kernel_launch(void* const* d_in, const int* in_sizes, int n_in,
                              void* d_out, int out_size) {
    const float* x     = (const float*)d_in[0];
    const float* pkv   = (const float*)d_in[1];
    const float* skv   = (const float*)d_in[2];
    const float* mkv   = (const float*)d_in[3];
    const float* qmask = (const float*)d_in[4];
    const float* pmask = (const float*)d_in[5];
    const float* smask = (const float*)d_in[6];
    const float* mmask = (const float*)d_in[7];
    const float* rmsw  = (const float*)d_in[8];
    const float* Wq  = (const float*)d_in[9];   const float* bq  = (const float*)d_in[10];
    const float* Wkp = (const float*)d_in[11];  const float* bkp = (const float*)d_in[12];
    const float* Wvp = (const float*)d_in[13];  const float* bvp = (const float*)d_in[14];
    const float* Wks = (const float*)d_in[15];  const float* bks = (const float*)d_in[16];
    const float* Wvs = (const float*)d_in[17];  const float* bvs = (const float*)d_in[18];
    const float* Wkm = (const float*)d_in[19];  const float* bkm = (const float*)d_in[20];
    const float* Wvm = (const float*)d_in[21];  const float* bvm = (const float*)d_in[22];
    const float* Wo  = (const float*)d_in[23];  const float* bo  = (const float*)d_in[24];
    const float* lng = (const float*)d_in[25];  const float* lnb = (const float*)d_in[26];
    const float* W1  = (const float*)d_in[27];  const float* W2  = (const float*)d_in[28];
    const float* ga  = (const float*)d_in[29];  const float* gf  = (const float*)d_in[30];
    float* out = (float*)d_out;

    float *qn, *qq, *kp, *ks, *km, *vp, *vs, *vm, *ctx, *hh, *ln, *ff;
    cudaGetSymbolAddress((void**)&qn,  g_qn);
    cudaGetSymbolAddress((void**)&qq,  g_q);
    cudaGetSymbolAddress((void**)&kp,  g_kp);
    cudaGetSymbolAddress((void**)&ks,  g_ks);
    cudaGetSymbolAddress((void**)&km,  g_km);
    cudaGetSymbolAddress((void**)&vp,  g_vp);
    cudaGetSymbolAddress((void**)&vs,  g_vs);
    cudaGetSymbolAddress((void**)&vm,  g_vm);
    cudaGetSymbolAddress((void**)&ctx, g_ctx);
    cudaGetSymbolAddress((void**)&hh,  g_h);
    cudaGetSymbolAddress((void**)&ln,  g_ln);
    cudaGetSymbolAddress((void**)&ff,  g_ff);

    const float scale = 0.25f;  // H^-0.5 = 16^-0.5

    // 1) RMSNorm
    rmsnorm_k<<<B_ * SQ_, 256>>>(x, rmsw, qn);

    // 2) projections (scale folded into Q)
    sgemm<0><<<dim3(16, 16), 256>>>(qn,  Wq,  bq,  nullptr, nullptr, qq, 2048, 2048, 2048, scale);
    sgemm<0><<<dim3(16, 16), 256>>>(pkv, Wkp, bkp, nullptr, nullptr, kp, 2048, 2048, 1280, 1.f);
    sgemm<0><<<dim3(16, 16), 256>>>(pkv, Wvp, bvp, nullptr, nullptr, vp, 2048, 2048, 1280, 1.f);
    sgemm<0><<<dim3(16, 16), 256>>>(skv, Wks, bks, nullptr, nullptr, ks, 2048, 2048, 1024, 1.f);
    sgemm<0><<<dim3(16, 16), 256>>>(skv, Wvs, bvs, nullptr, nullptr, vs, 2048, 2048, 1024, 1.f);
    sgemm<0><<<dim3(16,  8), 256>>>(mkv, Wkm, bkm, nullptr, nullptr, km, 1024, 2048,  768, 1.f);
    sgemm<0><<<dim3(16,  8), 256>>>(mkv, Wvm, bvm, nullptr, nullptr, vm, 1024, 2048,  768, 1.f);

    // 3) attention
    cudaFuncSetAttribute(attn_kernel, cudaFuncAttributeMaxDynamicSharedMemorySize, ATTN_SMEM);
    attn_kernel<<<dim3(16, 16, 2), 256, ATTN_SMEM>>>(qq, kp, ks, km, vp, vs, vm,
                                                     qmask, pmask, smask, mmask, ctx);

    // 4) h = x + tanh(ga)*(ctx@Wo + bo)
    sgemm<1><<<dim3(16, 16), 256>>>(ctx, Wo, bo, x, ga, hh, 2048, 2048, 2048, 1.f);

    // 5) LayerNorm
    layernorm_k<<<B_ * SQ_, 256>>>(hh, lng, lnb, ln);

    // 6) FFW: gelu(ln@W1) @ W2, gated residual
    sgemm<2><<<dim3(64, 16), 256>>>(ln, W1, nullptr, nullptr, nullptr, ff, 2048, INNER_, 2048, 1.f);
    sgemm<3><<<dim3(16, 16), 256>>>(ff, W2, nullptr, hh, gf, out, 2048, 2048, INNER_, 1.f);
}

// round 3
// speedup vs baseline: 2.2132x; 2.2132x over previous
#include <cuda_runtime.h>
#include <cuda_bf16.h>
#include <math.h>
#include <stdint.h>

typedef __nv_bfloat16 bf16;

// ---------------- problem dims ----------------
#define B_    2
#define SQ_   1024
#define D_    2048
#define H_    16
#define HD_   128
#define SP_   1024
#define SS_   1024
#define SM_   512
#define SKV_  2560
#define DP_   1280
#define DS_   1024
#define DM_   768
#define INNER_ 8192

// ---------------- scratch (device globals; no allocations) ----------------
__device__ float g_q  [B_*SQ_*D_];
__device__ float g_kp [B_*SP_*D_];
__device__ float g_ks [B_*SS_*D_];
__device__ float g_km [B_*SM_*D_];
__device__ float g_vp [B_*SP_*D_];
__device__ float g_vs [B_*SS_*D_];
__device__ float g_vm [B_*SM_*D_];
__device__ float g_ctx[B_*SQ_*D_];
__device__ float g_h  [B_*SQ_*D_];
// bf16 activation splits (hi/lo)
__device__ bf16 g_qn_h [B_*SQ_*D_];   __device__ bf16 g_qn_l [B_*SQ_*D_];
__device__ bf16 g_ap_h [B_*SP_*DP_];  __device__ bf16 g_ap_l [B_*SP_*DP_];
__device__ bf16 g_as_h [B_*SS_*DS_];  __device__ bf16 g_as_l [B_*SS_*DS_];
__device__ bf16 g_am_h [B_*SM_*DM_];  __device__ bf16 g_am_l [B_*SM_*DM_];
__device__ bf16 g_cx_h [B_*SQ_*D_];   __device__ bf16 g_cx_l [B_*SQ_*D_];
__device__ bf16 g_ln_h [B_*SQ_*D_];   __device__ bf16 g_ln_l [B_*SQ_*D_];
__device__ bf16 g_ff_h [B_*SQ_*INNER_]; __device__ bf16 g_ff_l [B_*SQ_*INNER_];
// bf16 transposed weight splits [N,K]
__device__ bf16 g_Wq_h [D_*D_];       __device__ bf16 g_Wq_l [D_*D_];
__device__ bf16 g_Wkp_h[D_*DP_];      __device__ bf16 g_Wkp_l[D_*DP_];
__device__ bf16 g_Wvp_h[D_*DP_];      __device__ bf16 g_Wvp_l[D_*DP_];
__device__ bf16 g_Wks_h[D_*DS_];      __device__ bf16 g_Wks_l[D_*DS_];
__device__ bf16 g_Wvs_h[D_*DS_];      __device__ bf16 g_Wvs_l[D_*DS_];
__device__ bf16 g_Wkm_h[D_*DM_];      __device__ bf16 g_Wkm_l[D_*DM_];
__device__ bf16 g_Wvm_h[D_*DM_];      __device__ bf16 g_Wvm_l[D_*DM_];
__device__ bf16 g_Wo_h [D_*D_];       __device__ bf16 g_Wo_l [D_*D_];
__device__ bf16 g_W1_h [INNER_*D_];   __device__ bf16 g_W1_l [INNER_*D_];
__device__ bf16 g_W2_h [D_*INNER_];   __device__ bf16 g_W2_l [D_*INNER_];

// ---------------- helpers ----------------
__device__ __forceinline__ uint32_t s2u(const void* p) {
    uint32_t a;
    asm("{ .reg .u64 t; cvta.to.shared.u64 t, %1; cvt.u32.u64 %0, t; }" : "=r"(a) : "l"(p));
    return a;
}
__device__ __forceinline__ void cp16(uint32_t s, const void* g) {
    asm volatile("cp.async.cg.shared.global [%0], [%1], 16;" :: "r"(s), "l"(g) : "memory");
}
#define LDSM4(r0, r1, r2, r3, addr) \
    asm volatile("ldmatrix.sync.aligned.m8n8.x4.shared.b16 {%0,%1,%2,%3}, [%4];" \
                 : "=r"(r0), "=r"(r1), "=r"(r2), "=r"(r3) : "r"(addr))
#define MMA16816(d, a, b) \
    asm volatile("mma.sync.aligned.m16n8k16.row.col.f32.bf16.bf16.f32 " \
                 "{%0,%1,%2,%3},{%4,%5,%6,%7},{%8,%9},{%0,%1,%2,%3};" \
                 : "+f"((d)[0]), "+f"((d)[1]), "+f"((d)[2]), "+f"((d)[3]) \
                 : "r"((a)[0]), "r"((a)[1]), "r"((a)[2]), "r"((a)[3]), \
                   "r"((b)[0]), "r"((b)[1]))

__device__ __forceinline__ float gelu_f(float x) {
    return 0.5f * x * (1.0f + erff(x * 0.70710678118654752f));
}
__device__ __forceinline__ void bsplit(float v, bf16* h, bf16* l) {
    bf16 hh = __float2bfloat16(v);
    *h = hh;
    *l = __float2bfloat16(v - __bfloat162float(hh));
}

// ---------------- block reduce ----------------
__device__ __forceinline__ float blockReduceSum(float v) {
    __shared__ float sh[32];
    __syncthreads();
    int lane = threadIdx.x & 31, w = threadIdx.x >> 5;
    #pragma unroll
    for (int o = 16; o > 0; o >>= 1) v += __shfl_xor_sync(0xffffffffu, v, o);
    if (lane == 0) sh[w] = v;
    __syncthreads();
    float r = 0.f;
    if (threadIdx.x < (blockDim.x >> 5)) r = sh[threadIdx.x];
    if (w == 0) {
        #pragma unroll
        for (int o = 16; o > 0; o >>= 1) r += __shfl_xor_sync(0xffffffffu, r, o);
        if (lane == 0) sh[0] = r;
    }
    __syncthreads();
    return sh[0];
}

// ---------------- RMSNorm -> bf16 split ----------------
__global__ __launch_bounds__(256) void rmsnorm_split(const float* __restrict__ x,
                                                     const float* __restrict__ w,
                                                     bf16* __restrict__ yh,
                                                     bf16* __restrict__ yl) {
    int row = blockIdx.x;
    const float* xr = x + (size_t)row * D_;
    float ss = 0.f;
    for (int t = threadIdx.x; t < D_; t += 256) { float v = xr[t]; ss += v * v; }
    ss = blockReduceSum(ss);
    float inv = rsqrtf(ss / (float)D_ + 1e-6f);
    for (int t = threadIdx.x; t < D_; t += 256) {
        float v = xr[t] * inv * w[t];
        bsplit(v, yh + (size_t)row * D_ + t, yl + (size_t)row * D_ + t);
    }
}

// ---------------- LayerNorm -> bf16 split ----------------
__global__ __launch_bounds__(256) void layernorm_split(const float* __restrict__ x,
                                                       const float* __restrict__ gg,
                                                       const float* __restrict__ bb,
                                                       bf16* __restrict__ yh,
                                                       bf16* __restrict__ yl) {
    int row = blockIdx.x;
    const float* xr = x + (size_t)row * D_;
    float s = 0.f;
    for (int t = threadIdx.x; t < D_; t += 256) s += xr[t];
    s = blockReduceSum(s);
    float mu = s / (float)D_;
    float vs = 0.f;
    for (int t = threadIdx.x; t < D_; t += 256) { float d = xr[t] - mu; vs += d * d; }
    vs = blockReduceSum(vs);
    float inv = rsqrtf(vs / (float)D_ + 1e-5f);
    for (int t = threadIdx.x; t < D_; t += 256) {
        float v = (xr[t] - mu) * inv * gg[t] + bb[t];
        bsplit(v, yh + (size_t)row * D_ + t, yl + (size_t)row * D_ + t);
    }
}

// ---------------- elementwise bf16 split ----------------
__global__ __launch_bounds__(256) void split_k(const float* __restrict__ x,
                                               bf16* __restrict__ h,
                                               bf16* __restrict__ l, int n) {
    int i = blockIdx.x * 256 + threadIdx.x;
    if (i < n) { bsplit(x[i], h + i, l + i); }
}

// ---------------- weight transpose+split: W[K,N] -> T[N,K] hi/lo ----------------
__global__ __launch_bounds__(256) void wsplit_T(const float* __restrict__ W,
                                                bf16* __restrict__ Th,
                                                bf16* __restrict__ Tl,
                                                int K, int N) {
    __shared__ float tile[32][33];
    int n0 = blockIdx.x * 32, k0 = blockIdx.y * 32;
    int tx = threadIdx.x, ty = threadIdx.y;
    #pragma unroll
    for (int i = ty; i < 32; i += 8)
        tile[i][tx] = W[(size_t)(k0 + i) * N + n0 + tx];
    __syncthreads();
    #pragma unroll
    for (int i = ty; i < 32; i += 8) {
        float v = tile[tx][i];
        size_t o = (size_t)(n0 + i) * K + k0 + tx;
        bsplit(v, Th + o, Tl + o);
    }
}

// ---------------- mma.sync GEMM: C[M,N] = A[M,K] @ T[N,K]^T (3-term bf16) ----------------
// EPI 0: Cf = acc + bias
// EPI 1: Cf = (acc + bias) * scale
// EPI 2: Cf = res + tanh(gate)*(acc + bias)
// EPI 3: Ch/Cl = bsplit(gelu(acc))
// EPI 4: Cf = res + tanh(gate)*acc
#define GB_M 128
#define GB_N 128
#define GB_K 64
#define STAGE_BYTES 65536           // Ah 16K | Al 16K | Bh 16K | Bl 16K
#define GEMM_SMEM (2 * STAGE_BYTES)

template <int EPI>
__global__ __launch_bounds__(256) void gemm_mma(
    const bf16* __restrict__ Ah, const bf16* __restrict__ Al,
    const bf16* __restrict__ Bh, const bf16* __restrict__ Bl,
    const float* __restrict__ bias, const float* __restrict__ res,
    const float* __restrict__ gate,
    float* __restrict__ Cf, bf16* __restrict__ Ch, bf16* __restrict__ Cl,
    int M, int N, int K, float scale) {
    extern __shared__ __align__(1024) char smem[];
    uint32_t sb = s2u(smem);
    const int tid = threadIdx.x, wid = tid >> 5, lane = tid & 31;
    const int n0 = blockIdx.x * GB_N, m0 = blockIdx.y * GB_M;
    const int wm0 = (wid >> 2) * 64;      // warp m-offset in tile
    const int wn0 = (wid & 3) * 32;       // warp n-offset in tile

    // ---- stage loader: 4 arrays of [128 rows x 64 bf16] with SW128 swizzle ----
    auto stage_load = [&](int st, int k0) {
        uint32_t s0 = sb + st * STAGE_BYTES;
        #pragma unroll
        for (int i = 0; i < 4; i++) {
            int idx = tid + 256 * i;
            int r = idx >> 3, c = idx & 7;
            uint32_t byte = r * 128 + c * 16;
            uint32_t sw = byte ^ ((byte >> 3) & 0x70);
            size_t goA = (size_t)(m0 + r) * K + k0 + c * 8;
            size_t goB = (size_t)(n0 + r) * K + k0 + c * 8;
            cp16(s0 + sw,         Ah + goA);
            cp16(s0 + 16384 + sw, Al + goA);
            cp16(s0 + 32768 + sw, Bh + goB);
            cp16(s0 + 49152 + sw, Bl + goB);
        }
        asm volatile("cp.async.commit_group;" ::: "memory");
    };

    float acc[4][4][4];
    #pragma unroll
    for (int i = 0; i < 4; i++)
        #pragma unroll
        for (int j = 0; j < 4; j++)
            #pragma unroll
            for (int c = 0; c < 4; c++) acc[i][j][c] = 0.f;

    const int nIter = K / GB_K;
    stage_load(0, 0);

    // lane-derived ldmatrix address components
    const int a_row = lane & 15;
    const int a_ch  = lane >> 4;
    const int b_row = (lane & 7) + ((lane >> 4) & 1) * 8;
    const int b_ch  = (lane >> 3) & 1;

    for (int it = 0; it < nIter; ++it) {
        if (it + 1 < nIter) stage_load((it + 1) & 1, (it + 1) * GB_K);
        if (it + 1 < nIter) {
            asm volatile("cp.async.wait_group 1;" ::: "memory");
        } else {
            asm volatile("cp.async.wait_group 0;" ::: "memory");
        }
        __syncthreads();

        uint32_t s0 = sb + (it & 1) * STAGE_BYTES;
        uint32_t sAh = s0, sAl = s0 + 16384, sBh = s0 + 32768, sBl = s0 + 49152;

        #pragma unroll
        for (int ks = 0; ks < 4; ks++) {
            uint32_t ahi[4][4], alo[4][4], bhi[4][2], blo[4][2];
            #pragma unroll
            for (int i = 0; i < 4; i++) {
                uint32_t byte = (wm0 + i * 16 + a_row) * 128 + (ks * 2 + a_ch) * 16;
                uint32_t sw = byte ^ ((byte >> 3) & 0x70);
                LDSM4(ahi[i][0], ahi[i][1], ahi[i][2], ahi[i][3], sAh + sw);
                LDSM4(alo[i][0], alo[i][1], alo[i][2], alo[i][3], sAl + sw);
            }
            #pragma unroll
            for (int jj = 0; jj < 2; jj++) {
                uint32_t byte = (wn0 + jj * 16 + b_row) * 128 + (ks * 2 + b_ch) * 16;
                uint32_t sw = byte ^ ((byte >> 3) & 0x70);
                uint32_t r0, r1, r2, r3;
                LDSM4(r0, r1, r2, r3, sBh + sw);
                bhi[jj * 2][0] = r0; bhi[jj * 2][1] = r1;
                bhi[jj * 2 + 1][0] = r2; bhi[jj * 2 + 1][1] = r3;
                LDSM4(r0, r1, r2, r3, sBl + sw);
                blo[jj * 2][0] = r0; blo[jj * 2][1] = r1;
                blo[jj * 2 + 1][0] = r2; blo[jj * 2 + 1][1] = r3;
            }
            #pragma unroll
            for (int i = 0; i < 4; i++)
                #pragma unroll
                for (int j = 0; j < 4; j++) {
                    MMA16816(acc[i][j], ahi[i], bhi[j]);
                    MMA16816(acc[i][j], ahi[i], blo[j]);
                    MMA16816(acc[i][j], alo[i], bhi[j]);
                }
        }
        __syncthreads();
    }

    // ---------- epilogue (direct from C fragments) ----------
    float gt = 0.f;
    if (EPI == 2 || EPI == 4) gt = tanhf(gate[0]);
    const int cr = lane >> 2;          // row within m16
    const int cc = (lane & 3) * 2;     // col within n8

    #pragma unroll
    for (int i = 0; i < 4; i++) {
        #pragma unroll
        for (int j = 0; j < 4; j++) {
            int gcol = n0 + wn0 + j * 8 + cc;
            #pragma unroll
            for (int half = 0; half < 2; half++) {
                int grow = m0 + wm0 + i * 16 + cr + half * 8;
                float v0 = acc[i][j][half * 2 + 0];
                float v1 = acc[i][j][half * 2 + 1];
                size_t o = (size_t)grow * N + gcol;
                if (EPI == 0) {
                    float2 r = make_float2(v0 + bias[gcol], v1 + bias[gcol + 1]);
                    *(float2*)(Cf + o) = r;
                } else if (EPI == 1) {
                    float2 r = make_float2((v0 + bias[gcol]) * scale,
                                           (v1 + bias[gcol + 1]) * scale);
                    *(float2*)(Cf + o) = r;
                } else if (EPI == 2) {
                    float2 rr = *(const float2*)(res + o);
                    float2 r = make_float2(rr.x + gt * (v0 + bias[gcol]),
                                           rr.y + gt * (v1 + bias[gcol + 1]));
                    *(float2*)(Cf + o) = r;
                } else if (EPI == 3) {
                    float a0 = gelu_f(v0), a1 = gelu_f(v1);
                    bf16 h0, l0, h1, l1;
                    bsplit(a0, &h0, &l0);
                    bsplit(a1, &h1, &l1);
                    *(__nv_bfloat162*)(Ch + o) = __nv_bfloat162(h0, h1);
                    *(__nv_bfloat162*)(Cl + o) = __nv_bfloat162(l0, l1);
                } else {
                    float2 rr = *(const float2*)(res + o);
                    float2 r = make_float2(rr.x + gt * v0, rr.y + gt * v1);
                    *(float2*)(Cf + o) = r;
                }
            }
        }
    }
}

// ---------------- flash attention (fp32, unchanged) ----------------
#define ATTN_SMEM ((2 * 64 * 132 + 64 * 68) * 4)

__global__ __launch_bounds__(256) void attn_kernel(
    const float* __restrict__ q,
    const float* __restrict__ kp, const float* __restrict__ ksg, const float* __restrict__ kmg,
    const float* __restrict__ vp, const float* __restrict__ vsg, const float* __restrict__ vmg,
    const float* __restrict__ qmask, const float* __restrict__ pmask,
    const float* __restrict__ smask, const float* __restrict__ mmask,
    float* __restrict__ ctx) {
    extern __shared__ float smf[];
    float* Qs  = smf;
    float* KVs = smf + 64 * 132;
    float* Ps  = smf + 2 * 64 * 132;

    const int qt = blockIdx.x;
    const int h  = blockIdx.y;
    const int b  = blockIdx.z;
    const int q0 = qt * 64;
    const int tid = threadIdx.x;
    const int tx = tid & 15, ty = tid >> 4;

    const float* Qg = q + ((size_t)(b * SQ_ + q0)) * D_ + h * HD_;
    for (int t = tid; t < 64 * 32; t += 256) {
        int r = t >> 5, c4 = (t & 31);
        *(float4*)(Qs + r * 132 + c4 * 4) = *(const float4*)(Qg + (size_t)r * D_ + c4 * 4);
    }

    float m[4], l[4], acc[4][8];
    #pragma unroll
    for (int i = 0; i < 4; i++) {
        m[i] = -1e30f; l[i] = 0.f;
        #pragma unroll
        for (int j = 0; j < 8; j++) acc[i][j] = 0.f;
    }
    float qm[4];
    #pragma unroll
    for (int i = 0; i < 4; i++) qm[i] = qmask[b * SQ_ + q0 + ty * 4 + i];

    const float4* Q4 = (const float4*)Qs;
    const float4* K4 = (const float4*)KVs;

    for (int kv0 = 0; kv0 < SKV_; kv0 += 64) {
        const float *Kseg, *Vseg, *mseg;
        int sr;
        if (kv0 < SP_) {
            Kseg = kp + (size_t)b * SP_ * D_; Vseg = vp + (size_t)b * SP_ * D_;
            mseg = pmask + b * SP_; sr = kv0;
        } else if (kv0 < SP_ + SS_) {
            Kseg = ksg + (size_t)b * SS_ * D_; Vseg = vsg + (size_t)b * SS_ * D_;
            mseg = smask + b * SS_; sr = kv0 - SP_;
        } else {
            Kseg = kmg + (size_t)b * SM_ * D_; Vseg = vmg + (size_t)b * SM_ * D_;
            mseg = mmask + b * SM_; sr = kv0 - SP_ - SS_;
        }

        __syncthreads();
        const float* Kg = Kseg + (size_t)sr * D_ + h * HD_;
        for (int t = tid; t < 64 * 32; t += 256) {
            int r = t >> 5, c4 = (t & 31);
            *(float4*)(KVs + r * 132 + c4 * 4) = *(const float4*)(Kg + (size_t)r * D_ + c4 * 4);
        }
        __syncthreads();

        float s[4][4];
        #pragma unroll
        for (int i = 0; i < 4; i++)
            #pragma unroll
            for (int j = 0; j < 4; j++) s[i][j] = 0.f;

        #pragma unroll 4
        for (int k4 = 0; k4 < 32; k4++) {
            float4 qv[4], kv[4];
            #pragma unroll
            for (int i = 0; i < 4; i++) qv[i] = Q4[(ty * 4 + i) * 33 + k4];
            #pragma unroll
            for (int j = 0; j < 4; j++) kv[j] = K4[(tx + 16 * j) * 33 + k4];
            #pragma unroll
            for (int i = 0; i < 4; i++)
                #pragma unroll
                for (int j = 0; j < 4; j++)
                    s[i][j] += qv[i].x * kv[j].x + qv[i].y * kv[j].y +
                               qv[i].z * kv[j].z + qv[i].w * kv[j].w;
        }

        float kmv[4];
        #pragma unroll
        for (int j = 0; j < 4; j++) kmv[j] = mseg[sr + tx + 16 * j];
        #pragma unroll
        for (int i = 0; i < 4; i++)
            #pragma unroll
            for (int j = 0; j < 4; j++)
                if (qm[i] == 0.f || kmv[j] == 0.f) s[i][j] = -3.0e38f;

        #pragma unroll
        for (int i = 0; i < 4; i++) {
            float mx = fmaxf(fmaxf(s[i][0], s[i][1]), fmaxf(s[i][2], s[i][3]));
            #pragma unroll
            for (int o = 8; o > 0; o >>= 1)
                mx = fmaxf(mx, __shfl_xor_sync(0xffffffffu, mx, o, 16));
            float mn = fmaxf(m[i], mx);
            float alpha = expf(m[i] - mn);
            float ps = 0.f;
            #pragma unroll
            for (int j = 0; j < 4; j++) {
                float p = expf(s[i][j] - mn);
                Ps[(ty * 4 + i) * 68 + tx + 16 * j] = p;
                ps += p;
            }
            #pragma unroll
            for (int o = 8; o > 0; o >>= 1)
                ps += __shfl_xor_sync(0xffffffffu, ps, o, 16);
            l[i] = l[i] * alpha + ps;
            m[i] = mn;
            #pragma unroll
            for (int j = 0; j < 8; j++) acc[i][j] *= alpha;
        }
        __syncthreads();

        const float* Vg = Vseg + (size_t)sr * D_ + h * HD_;
        for (int t = tid; t < 64 * 32; t += 256) {
            int r = t >> 5, c4 = (t & 31);
            *(float4*)(KVs + r * 132 + c4 * 4) = *(const float4*)(Vg + (size_t)r * D_ + c4 * 4);
        }
        __syncthreads();

        #pragma unroll 2
        for (int kk = 0; kk < 64; kk++) {
            float pv[4];
            #pragma unroll
            for (int i = 0; i < 4; i++) pv[i] = Ps[(ty * 4 + i) * 68 + kk];
            #pragma unroll
            for (int j = 0; j < 8; j++) {
                float vv = KVs[kk * 132 + tx + 16 * j];
                #pragma unroll
                for (int i = 0; i < 4; i++) acc[i][j] += pv[i] * vv;
            }
        }
    }

    float* Og = ctx + ((size_t)(b * SQ_ + q0)) * D_ + h * HD_;
    #pragma unroll
    for (int i = 0; i < 4; i++) {
        float inv = 1.0f / l[i];
        #pragma unroll
        for (int j = 0; j < 8; j++)
            Og[(size_t)(ty * 4 + i) * D_ + tx + 16 * j] = acc[i][j] * inv;
    }
}

// ---------------- launcher ----------------
extern "C" void kernel_launch(void* const* d_in, const int* in_sizes, int n_in,
                              void* d_out, int out_size) {
    const float* x     = (const float*)d_in[0];
    const float* pkv   = (const float*)d_in[1];
    const float* skv   = (const float*)d_in[2];
    const float* mkv   = (const float*)d_in[3];
    const float* qmask = (const float*)d_in[4];
    const float* pmask = (const float*)d_in[5];
    const float* smask = (const float*)d_in[6];
    const float* mmask = (const float*)d_in[7];
    const float* rmsw  = (const float*)d_in[8];
    const float* Wq  = (const float*)d_in[9];   const float* bq  = (const float*)d_in[10];
    const float* Wkp = (const float*)d_in[11];  const float* bkp = (const float*)d_in[12];
    const float* Wvp = (const float*)d_in[13];  const float* bvp = (const float*)d_in[14];
    const float* Wks = (const float*)d_in[15];  const float* bks = (const float*)d_in[16];
    const float* Wvs = (const float*)d_in[17];  const float* bvs = (const float*)d_in[18];
    const float* Wkm = (const float*)d_in[19];  const float* bkm = (const float*)d_in[20];
    const float* Wvm = (const float*)d_in[21];  const float* bvm = (const float*)d_in[22];
    const float* Wo  = (const float*)d_in[23];  const float* bo  = (const float*)d_in[24];
    const float* lng = (const float*)d_in[25];  const float* lnb = (const float*)d_in[26];
    const float* W1  = (const float*)d_in[27];  const float* W2  = (const float*)d_in[28];
    const float* ga  = (const float*)d_in[29];  const float* gf  = (const float*)d_in[30];
    float* out = (float*)d_out;

    float *q, *kp, *ks, *km, *vp, *vs, *vm, *ctx, *hh;
    cudaGetSymbolAddress((void**)&q,   g_q);
    cudaGetSymbolAddress((void**)&kp,  g_kp);
    cudaGetSymbolAddress((void**)&ks,  g_ks);
    cudaGetSymbolAddress((void**)&km,  g_km);
    cudaGetSymbolAddress((void**)&vp,  g_vp);
    cudaGetSymbolAddress((void**)&vs,  g_vs);
    cudaGetSymbolAddress((void**)&vm,  g_vm);
    cudaGetSymbolAddress((void**)&ctx, g_ctx);
    cudaGetSymbolAddress((void**)&hh,  g_h);

    bf16 *qnh,*qnl,*aph,*apl,*ash,*asl,*amh,*aml,*cxh,*cxl,*lnh,*lnl,*ffh,*ffl;
    cudaGetSymbolAddress((void**)&qnh, g_qn_h);  cudaGetSymbolAddress((void**)&qnl, g_qn_l);
    cudaGetSymbolAddress((void**)&aph, g_ap_h);  cudaGetSymbolAddress((void**)&apl, g_ap_l);
    cudaGetSymbolAddress((void**)&ash, g_as_h);  cudaGetSymbolAddress((void**)&asl, g_as_l);
    cudaGetSymbolAddress((void**)&amh, g_am_h);  cudaGetSymbolAddress((void**)&aml, g_am_l);
    cudaGetSymbolAddress((void**)&cxh, g_cx_h);  cudaGetSymbolAddress((void**)&cxl, g_cx_l);
    cudaGetSymbolAddress((void**)&lnh, g_ln_h);  cudaGetSymbolAddress((void**)&lnl, g_ln_l);
    cudaGetSymbolAddress((void**)&ffh, g_ff_h);  cudaGetSymbolAddress((void**)&ffl, g_ff_l);

    bf16 *tWqh,*tWql,*tWkph,*tWkpl,*tWvph,*tWvpl,*tWksh,*tWksl,*tWvsh,*tWvsl;
    bf16 *tWkmh,*tWkml,*tWvmh,*tWvml,*tWoh,*tWol,*tW1h,*tW1l,*tW2h,*tW2l;
    cudaGetSymbolAddress((void**)&tWqh,  g_Wq_h);   cudaGetSymbolAddress((void**)&tWql,  g_Wq_l);
    cudaGetSymbolAddress((void**)&tWkph, g_Wkp_h);  cudaGetSymbolAddress((void**)&tWkpl, g_Wkp_l);
    cudaGetSymbolAddress((void**)&tWvph, g_Wvp_h);  cudaGetSymbolAddress((void**)&tWvpl, g_Wvp_l);
    cudaGetSymbolAddress((void**)&tWksh, g_Wks_h);  cudaGetSymbolAddress((void**)&tWksl, g_Wks_l);
    cudaGetSymbolAddress((void**)&tWvsh, g_Wvs_h);  cudaGetSymbolAddress((void**)&tWvsl, g_Wvs_l);
    cudaGetSymbolAddress((void**)&tWkmh, g_Wkm_h);  cudaGetSymbolAddress((void**)&tWkml, g_Wkm_l);
    cudaGetSymbolAddress((void**)&tWvmh, g_Wvm_h);  cudaGetSymbolAddress((void**)&tWvml, g_Wvm_l);
    cudaGetSymbolAddress((void**)&tWoh,  g_Wo_h);   cudaGetSymbolAddress((void**)&tWol,  g_Wo_l);
    cudaGetSymbolAddress((void**)&tW1h,  g_W1_h);   cudaGetSymbolAddress((void**)&tW1l,  g_W1_l);
    cudaGetSymbolAddress((void**)&tW2h,  g_W2_h);   cudaGetSymbolAddress((void**)&tW2l,  g_W2_l);

    cudaFuncSetAttribute(gemm_mma<0>, cudaFuncAttributeMaxDynamicSharedMemorySize, GEMM_SMEM);
    cudaFuncSetAttribute(gemm_mma<1>, cudaFuncAttributeMaxDynamicSharedMemorySize, GEMM_SMEM);
    cudaFuncSetAttribute(gemm_mma<2>, cudaFuncAttributeMaxDynamicSharedMemorySize, GEMM_SMEM);
    cudaFuncSetAttribute(gemm_mma<3>, cudaFuncAttributeMaxDynamicSharedMemorySize, GEMM_SMEM);
    cudaFuncSetAttribute(gemm_mma<4>, cudaFuncAttributeMaxDynamicSharedMemorySize, GEMM_SMEM);
    cudaFuncSetAttribute(attn_kernel, cudaFuncAttributeMaxDynamicSharedMemorySize, ATTN_SMEM);

    dim3 tb(32, 8);

    // weight transpose+split
    wsplit_T<<<dim3(D_ / 32,     D_ / 32),     tb>>>(Wq,  tWqh,  tWql,  D_,     D_);
    wsplit_T<<<dim3(D_ / 32,     DP_ / 32),    tb>>>(Wkp, tWkph, tWkpl, DP_,    D_);
    wsplit_T<<<dim3(D_ / 32,     DP_ / 32),    tb>>>(Wvp, tWvph, tWvpl, DP_,    D_);
    wsplit_T<<<dim3(D_ / 32,     DS_ / 32),    tb>>>(Wks, tWksh, tWksl, DS_,    D_);
    wsplit_T<<<dim3(D_ / 32,     DS_ / 32),    tb>>>(Wvs, tWvsh, tWvsl, DS_,    D_);
    wsplit_T<<<dim3(D_ / 32,     DM_ / 32),    tb>>>(Wkm, tWkmh, tWkml, DM_,    D_);
    wsplit_T<<<dim3(D_ / 32,     DM_ / 32),    tb>>>(Wvm, tWvmh, tWvml, DM_,    D_);
    wsplit_T<<<dim3(D_ / 32,     D_ / 32),     tb>>>(Wo,  tWoh,  tWol,  D_,     D_);
    wsplit_T<<<dim3(INNER_ / 32, D_ / 32),     tb>>>(W1,  tW1h,  tW1l,  D_,     INNER_);
    wsplit_T<<<dim3(D_ / 32,     INNER_ / 32), tb>>>(W2,  tW2h,  tW2l,  INNER_, D_);

    // activation splits
    rmsnorm_split<<<B_ * SQ_, 256>>>(x, rmsw, qnh, qnl);
    split_k<<<(B_ * SP_ * DP_ + 255) / 256, 256>>>(pkv, aph, apl, B_ * SP_ * DP_);
    split_k<<<(B_ * SS_ * DS_ + 255) / 256, 256>>>(skv, ash, asl, B_ * SS_ * DS_);
    split_k<<<(B_ * SM_ * DM_ + 255) / 256, 256>>>(mkv, amh, aml, B_ * SM_ * DM_);

    // projections (Q scale folded)
    gemm_mma<1><<<dim3(16, 16), 256, GEMM_SMEM>>>(qnh, qnl, tWqh, tWql, bq, nullptr, nullptr,
                                                  q, nullptr, nullptr, 2048, 2048, 2048, 0.25f);
    gemm_mma<0><<<dim3(16, 16), 256, GEMM_SMEM>>>(aph, apl, tWkph, tWkpl, bkp, nullptr, nullptr,
                                                  kp, nullptr, nullptr, 2048, 2048, 1280, 1.f);
    gemm_mma<0><<<dim3(16, 16), 256, GEMM_SMEM>>>(aph, apl, tWvph, tWvpl, bvp, nullptr, nullptr,
                                                  vp, nullptr, nullptr, 2048, 2048, 1280, 1.f);
    gemm_mma<0><<<dim3(16, 16), 256, GEMM_SMEM>>>(ash, asl, tWksh, tWksl, bks, nullptr, nullptr,
                                                  ks, nullptr, nullptr, 2048, 2048, 1024, 1.f);
    gemm_mma<0><<<dim3(16, 16), 256, GEMM_SMEM>>>(ash, asl, tWvsh, tWvsl, bvs, nullptr, nullptr,
                                                  vs, nullptr, nullptr, 2048, 2048, 1024, 1.f);
    gemm_mma<0><<<dim3(16, 8), 256, GEMM_SMEM>>>(amh, aml, tWkmh, tWkml, bkm, nullptr, nullptr,
                                                 km, nullptr, nullptr, 1024, 2048, 768, 1.f);
    gemm_mma<0><<<dim3(16, 8), 256, GEMM_SMEM>>>(amh, aml, tWvmh, tWvml, bvm, nullptr, nullptr,
                                                 vm, nullptr, nullptr, 1024, 2048, 768, 1.f);

    // attention
    attn_kernel<<<dim3(16, 16, 2), 256, ATTN_SMEM>>>(q, kp, ks, km, vp, vs, vm,
                                                     qmask, pmask, smask, mmask, ctx);

    // h = x + tanh(ga)*(ctx@Wo + bo)
    split_k<<<(B_ * SQ_ * D_ + 255) / 256, 256>>>(ctx, cxh, cxl, B_ * SQ_ * D_);
    gemm_mma<2><<<dim3(16, 16), 256, GEMM_SMEM>>>(cxh, cxl, tWoh, tWol, bo, x, ga,
                                                  hh, nullptr, nullptr, 2048, 2048, 2048, 1.f);

    // LayerNorm
    layernorm_split<<<B_ * SQ_, 256>>>(hh, lng, lnb, lnh, lnl);

    // FFW
    gemm_mma<3><<<dim3(64, 16), 256, GEMM_SMEM>>>(lnh, lnl, tW1h, tW1l, nullptr, nullptr, nullptr,
                                                  nullptr, ffh, ffl, 2048, INNER_, 2048, 1.f);
    gemm_mma<4><<<dim3(16, 16), 256, GEMM_SMEM>>>(ffh, ffl, tW2h, tW2l, nullptr, hh, gf,
                                                  out, nullptr, nullptr, 2048, 2048, INNER_, 1.f);
}

// round 4
// speedup vs baseline: 3.0457x; 1.3761x over previous
#include <cuda_runtime.h>
#include <cuda_bf16.h>
#include <math.h>
#include <stdint.h>

typedef __nv_bfloat16 bf16;

// ---------------- problem dims ----------------
#define B_    2
#define SQ_   1024
#define D_    2048
#define H_    16
#define HD_   128
#define SP_   1024
#define SS_   1024
#define SM_   512
#define SKV_  2560
#define DP_   1280
#define DS_   1024
#define DM_   768
#define INNER_ 8192

// ---------------- scratch (device globals; no allocations) ----------------
__device__ float g_h  [B_*SQ_*D_];
__device__ float g_kvmask[B_*SKV_];
// bf16 activation splits (hi/lo)
__device__ bf16 g_qn_h [B_*SQ_*D_];   __device__ bf16 g_qn_l [B_*SQ_*D_];
__device__ bf16 g_ap_h [B_*SP_*DP_];  __device__ bf16 g_ap_l [B_*SP_*DP_];
__device__ bf16 g_as_h [B_*SS_*DS_];  __device__ bf16 g_as_l [B_*SS_*DS_];
__device__ bf16 g_am_h [B_*SM_*DM_];  __device__ bf16 g_am_l [B_*SM_*DM_];
__device__ bf16 g_qh   [B_*SQ_*D_];   __device__ bf16 g_ql   [B_*SQ_*D_];
__device__ bf16 g_kh   [B_*SKV_*D_];  __device__ bf16 g_kl   [B_*SKV_*D_];
__device__ bf16 g_vh   [B_*SKV_*D_];  __device__ bf16 g_vl   [B_*SKV_*D_];
__device__ bf16 g_cx_h [B_*SQ_*D_];   __device__ bf16 g_cx_l [B_*SQ_*D_];
__device__ bf16 g_ln_h [B_*SQ_*D_];   __device__ bf16 g_ln_l [B_*SQ_*D_];
__device__ bf16 g_ff_h [B_*SQ_*INNER_]; __device__ bf16 g_ff_l [B_*SQ_*INNER_];
// bf16 transposed weight splits [N,K]
__device__ bf16 g_Wq_h [D_*D_];       __device__ bf16 g_Wq_l [D_*D_];
__device__ bf16 g_Wkp_h[D_*DP_];      __device__ bf16 g_Wkp_l[D_*DP_];
__device__ bf16 g_Wvp_h[D_*DP_];      __device__ bf16 g_Wvp_l[D_*DP_];
__device__ bf16 g_Wks_h[D_*DS_];      __device__ bf16 g_Wks_l[D_*DS_];
__device__ bf16 g_Wvs_h[D_*DS_];      __device__ bf16 g_Wvs_l[D_*DS_];
__device__ bf16 g_Wkm_h[D_*DM_];      __device__ bf16 g_Wkm_l[D_*DM_];
__device__ bf16 g_Wvm_h[D_*DM_];      __device__ bf16 g_Wvm_l[D_*DM_];
__device__ bf16 g_Wo_h [D_*D_];       __device__ bf16 g_Wo_l [D_*D_];
__device__ bf16 g_W1_h [INNER_*D_];   __device__ bf16 g_W1_l [INNER_*D_];
__device__ bf16 g_W2_h [D_*INNER_];   __device__ bf16 g_W2_l [D_*INNER_];

// ---------------- helpers ----------------
__device__ __forceinline__ uint32_t s2u(const void* p) {
    uint32_t a;
    asm("{ .reg .u64 t; cvta.to.shared.u64 t, %1; cvt.u32.u64 %0, t; }" : "=r"(a) : "l"(p));
    return a;
}
__device__ __forceinline__ void cp16(uint32_t s, const void* g) {
    asm volatile("cp.async.cg.shared.global [%0], [%1], 16;" :: "r"(s), "l"(g) : "memory");
}
#define LDSM4(r0, r1, r2, r3, addr) \
    asm volatile("ldmatrix.sync.aligned.m8n8.x4.shared.b16 {%0,%1,%2,%3}, [%4];" \
                 : "=r"(r0), "=r"(r1), "=r"(r2), "=r"(r3) : "r"(addr))
#define LDSM4T(r0, r1, r2, r3, addr) \
    asm volatile("ldmatrix.sync.aligned.m8n8.x4.trans.shared.b16 {%0,%1,%2,%3}, [%4];" \
                 : "=r"(r0), "=r"(r1), "=r"(r2), "=r"(r3) : "r"(addr))
#define MMA16816(d, a, b) \
    asm volatile("mma.sync.aligned.m16n8k16.row.col.f32.bf16.bf16.f32 " \
                 "{%0,%1,%2,%3},{%4,%5,%6,%7},{%8,%9},{%0,%1,%2,%3};" \
                 : "+f"((d)[0]), "+f"((d)[1]), "+f"((d)[2]), "+f"((d)[3]) \
                 : "r"((a)[0]), "r"((a)[1]), "r"((a)[2]), "r"((a)[3]), \
                   "r"((b)[0]), "r"((b)[1]))

__device__ __forceinline__ float gelu_f(float x) {
    return 0.5f * x * (1.0f + erff(x * 0.70710678118654752f));
}
__device__ __forceinline__ void bsplit(float v, bf16* h, bf16* l) {
    bf16 hh = __float2bfloat16(v);
    *h = hh;
    *l = __float2bfloat16(v - __bfloat162float(hh));
}

// ---------------- block reduce ----------------
__device__ __forceinline__ float blockReduceSum(float v) {
    __shared__ float sh[32];
    __syncthreads();
    int lane = threadIdx.x & 31, w = threadIdx.x >> 5;
    #pragma unroll
    for (int o = 16; o > 0; o >>= 1) v += __shfl_xor_sync(0xffffffffu, v, o);
    if (lane == 0) sh[w] = v;
    __syncthreads();
    float r = 0.f;
    if (threadIdx.x < (blockDim.x >> 5)) r = sh[threadIdx.x];
    if (w == 0) {
        #pragma unroll
        for (int o = 16; o > 0; o >>= 1) r += __shfl_xor_sync(0xffffffffu, r, o);
        if (lane == 0) sh[0] = r;
    }
    __syncthreads();
    return sh[0];
}

// ---------------- RMSNorm / LayerNorm / splits ----------------
__global__ __launch_bounds__(256) void rmsnorm_split(const float* __restrict__ x,
                                                     const float* __restrict__ w,
                                                     bf16* __restrict__ yh,
                                                     bf16* __restrict__ yl) {
    int row = blockIdx.x;
    const float* xr = x + (size_t)row * D_;
    float ss = 0.f;
    for (int t = threadIdx.x; t < D_; t += 256) { float v = xr[t]; ss += v * v; }
    ss = blockReduceSum(ss);
    float inv = rsqrtf(ss / (float)D_ + 1e-6f);
    for (int t = threadIdx.x; t < D_; t += 256) {
        float v = xr[t] * inv * w[t];
        bsplit(v, yh + (size_t)row * D_ + t, yl + (size_t)row * D_ + t);
    }
}

__global__ __launch_bounds__(256) void layernorm_split(const float* __restrict__ x,
                                                       const float* __restrict__ gg,
                                                       const float* __restrict__ bb,
                                                       bf16* __restrict__ yh,
                                                       bf16* __restrict__ yl) {
    int row = blockIdx.x;
    const float* xr = x + (size_t)row * D_;
    float s = 0.f;
    for (int t = threadIdx.x; t < D_; t += 256) s += xr[t];
    s = blockReduceSum(s);
    float mu = s / (float)D_;
    float vs = 0.f;
    for (int t = threadIdx.x; t < D_; t += 256) { float d = xr[t] - mu; vs += d * d; }
    vs = blockReduceSum(vs);
    float inv = rsqrtf(vs / (float)D_ + 1e-5f);
    for (int t = threadIdx.x; t < D_; t += 256) {
        float v = (xr[t] - mu) * inv * gg[t] + bb[t];
        bsplit(v, yh + (size_t)row * D_ + t, yl + (size_t)row * D_ + t);
    }
}

__global__ __launch_bounds__(256) void split_k(const float* __restrict__ x,
                                               bf16* __restrict__ h,
                                               bf16* __restrict__ l, int n) {
    int i = blockIdx.x * 256 + threadIdx.x;
    if (i < n) { bsplit(x[i], h + i, l + i); }
}

__global__ __launch_bounds__(256) void maskcat_k(const float* __restrict__ pm,
                                                 const float* __restrict__ sm,
                                                 const float* __restrict__ mm,
                                                 float* __restrict__ out) {
    int i = blockIdx.x * 256 + threadIdx.x;
    if (i >= B_ * SKV_) return;
    int b = i / SKV_, s = i % SKV_;
    float v;
    if (s < SP_) v = pm[b * SP_ + s];
    else if (s < SP_ + SS_) v = sm[b * SS_ + s - SP_];
    else v = mm[b * SM_ + s - SP_ - SS_];
    out[i] = v;
}

// ---------------- weight transpose+split: W[K,N] -> T[N,K] hi/lo ----------------
__global__ __launch_bounds__(256) void wsplit_T(const float* __restrict__ W,
                                                bf16* __restrict__ Th,
                                                bf16* __restrict__ Tl,
                                                int K, int N) {
    __shared__ float tile[32][33];
    int n0 = blockIdx.x * 32, k0 = blockIdx.y * 32;
    int tx = threadIdx.x, ty = threadIdx.y;
    #pragma unroll
    for (int i = ty; i < 32; i += 8)
        tile[i][tx] = W[(size_t)(k0 + i) * N + n0 + tx];
    __syncthreads();
    #pragma unroll
    for (int i = ty; i < 32; i += 8) {
        float v = tile[tx][i];
        size_t o = (size_t)(n0 + i) * K + k0 + tx;
        bsplit(v, Th + o, Tl + o);
    }
}

// ---------------- mma.sync GEMM: C[M,N] = A[M,K] @ T[N,K]^T (3-term bf16) ----------------
// EPI 0: Cf = acc + bias
// EPI 2: Cf = res + tanh(gate)*(acc + bias)
// EPI 3: Ch/Cl = bsplit(gelu(acc))
// EPI 4: Cf = res + tanh(gate)*acc
// EPI 5: Ch/Cl = bsplit((acc+bias)*scale), with row remap (K/V concat)
#define GB_M 128
#define GB_N 128
#define GB_K 64
#define STAGE_BYTES 65536
#define GEMM_SMEM (2 * STAGE_BYTES)

template <int EPI>
__global__ __launch_bounds__(256) void gemm_mma(
    const bf16* __restrict__ Ah, const bf16* __restrict__ Al,
    const bf16* __restrict__ Bh, const bf16* __restrict__ Bl,
    const float* __restrict__ bias, const float* __restrict__ res,
    const float* __restrict__ gate,
    float* __restrict__ Cf, bf16* __restrict__ Ch, bf16* __restrict__ Cl,
    int M, int N, int K, float scale, int oShift, int oStride, int oOff) {
    extern __shared__ __align__(1024) char smem[];
    uint32_t sb = s2u(smem);
    const int tid = threadIdx.x, wid = tid >> 5, lane = tid & 31;
    const int n0 = blockIdx.x * GB_N, m0 = blockIdx.y * GB_M;
    const int wm0 = (wid >> 2) * 64;
    const int wn0 = (wid & 3) * 32;

    auto stage_load = [&](int st, int k0) {
        uint32_t s0 = sb + st * STAGE_BYTES;
        #pragma unroll
        for (int i = 0; i < 4; i++) {
            int idx = tid + 256 * i;
            int r = idx >> 3, c = idx & 7;
            uint32_t byte = r * 128 + c * 16;
            uint32_t sw = byte ^ ((byte >> 3) & 0x70);
            size_t goA = (size_t)(m0 + r) * K + k0 + c * 8;
            size_t goB = (size_t)(n0 + r) * K + k0 + c * 8;
            cp16(s0 + sw,         Ah + goA);
            cp16(s0 + 16384 + sw, Al + goA);
            cp16(s0 + 32768 + sw, Bh + goB);
            cp16(s0 + 49152 + sw, Bl + goB);
        }
        asm volatile("cp.async.commit_group;" ::: "memory");
    };

    float acc[4][4][4];
    #pragma unroll
    for (int i = 0; i < 4; i++)
        #pragma unroll
        for (int j = 0; j < 4; j++)
            #pragma unroll
            for (int c = 0; c < 4; c++) acc[i][j][c] = 0.f;

    const int nIter = K / GB_K;
    stage_load(0, 0);

    const int a_row = lane & 15;
    const int a_ch  = lane >> 4;
    const int b_row = (lane & 7) + ((lane >> 4) & 1) * 8;
    const int b_ch  = (lane >> 3) & 1;

    for (int it = 0; it < nIter; ++it) {
        if (it + 1 < nIter) stage_load((it + 1) & 1, (it + 1) * GB_K);
        if (it + 1 < nIter) {
            asm volatile("cp.async.wait_group 1;" ::: "memory");
        } else {
            asm volatile("cp.async.wait_group 0;" ::: "memory");
        }
        __syncthreads();

        uint32_t s0 = sb + (it & 1) * STAGE_BYTES;
        uint32_t sAh = s0, sAl = s0 + 16384, sBh = s0 + 32768, sBl = s0 + 49152;

        #pragma unroll
        for (int ks = 0; ks < 4; ks++) {
            uint32_t ahi[4][4], alo[4][4], bhi[4][2], blo[4][2];
            #pragma unroll
            for (int i = 0; i < 4; i++) {
                uint32_t byte = (wm0 + i * 16 + a_row) * 128 + (ks * 2 + a_ch) * 16;
                uint32_t sw = byte ^ ((byte >> 3) & 0x70);
                LDSM4(ahi[i][0], ahi[i][1], ahi[i][2], ahi[i][3], sAh + sw);
                LDSM4(alo[i][0], alo[i][1], alo[i][2], alo[i][3], sAl + sw);
            }
            #pragma unroll
            for (int jj = 0; jj < 2; jj++) {
                uint32_t byte = (wn0 + jj * 16 + b_row) * 128 + (ks * 2 + b_ch) * 16;
                uint32_t sw = byte ^ ((byte >> 3) & 0x70);
                uint32_t r0, r1, r2, r3;
                LDSM4(r0, r1, r2, r3, sBh + sw);
                bhi[jj * 2][0] = r0; bhi[jj * 2][1] = r1;
                bhi[jj * 2 + 1][0] = r2; bhi[jj * 2 + 1][1] = r3;
                LDSM4(r0, r1, r2, r3, sBl + sw);
                blo[jj * 2][0] = r0; blo[jj * 2][1] = r1;
                blo[jj * 2 + 1][0] = r2; blo[jj * 2 + 1][1] = r3;
            }
            #pragma unroll
            for (int i = 0; i < 4; i++)
                #pragma unroll
                for (int j = 0; j < 4; j++) {
                    MMA16816(acc[i][j], ahi[i], bhi[j]);
                    MMA16816(acc[i][j], ahi[i], blo[j]);
                    MMA16816(acc[i][j], alo[i], bhi[j]);
                }
        }
        __syncthreads();
    }

    float gt = 0.f;
    if (EPI == 2 || EPI == 4) gt = tanhf(gate[0]);
    const int cr = lane >> 2;
    const int cc = (lane & 3) * 2;

    #pragma unroll
    for (int i = 0; i < 4; i++) {
        #pragma unroll
        for (int j = 0; j < 4; j++) {
            int gcol = n0 + wn0 + j * 8 + cc;
            #pragma unroll
            for (int half = 0; half < 2; half++) {
                int grow = m0 + wm0 + i * 16 + cr + half * 8;
                float v0 = acc[i][j][half * 2 + 0];
                float v1 = acc[i][j][half * 2 + 1];
                size_t o = (size_t)grow * N + gcol;
                if (EPI == 0) {
                    *(float2*)(Cf + o) = make_float2(v0 + bias[gcol], v1 + bias[gcol + 1]);
                } else if (EPI == 2) {
                    float2 rr = *(const float2*)(res + o);
                    *(float2*)(Cf + o) = make_float2(rr.x + gt * (v0 + bias[gcol]),
                                                     rr.y + gt * (v1 + bias[gcol + 1]));
                } else if (EPI == 3) {
                    float a0 = gelu_f(v0), a1 = gelu_f(v1);
                    bf16 h0, l0, h1, l1;
                    bsplit(a0, &h0, &l0);
                    bsplit(a1, &h1, &l1);
                    *(__nv_bfloat162*)(Ch + o) = __nv_bfloat162(h0, h1);
                    *(__nv_bfloat162*)(Cl + o) = __nv_bfloat162(l0, l1);
                } else if (EPI == 4) {
                    float2 rr = *(const float2*)(res + o);
                    *(float2*)(Cf + o) = make_float2(rr.x + gt * v0, rr.y + gt * v1);
                } else {  // EPI 5
                    int ib = grow >> oShift;
                    int ir = grow & ((1 << oShift) - 1);
                    size_t oo = ((size_t)ib * oStride + oOff + ir) * N + gcol;
                    float a0 = (v0 + bias[gcol]) * scale;
                    float a1 = (v1 + bias[gcol + 1]) * scale;
                    bf16 h0, l0, h1, l1;
                    bsplit(a0, &h0, &l0);
                    bsplit(a1, &h1, &l1);
                    *(__nv_bfloat162*)(Ch + oo) = __nv_bfloat162(h0, h1);
                    *(__nv_bfloat162*)(Cl + oo) = __nv_bfloat162(l0, l1);
                }
            }
        }
    }
}

// ---------------- mma.sync flash attention ----------------
// BQ=64, BKV=64, HD=128, 256 threads.
// smem layout (bytes):
#define AOF_Q   0u
#define AOF_QL  16384u
#define AOF_KV  32768u            // per-stage 64KB: Kh|Kl|Vh|Vl (16K each), 2 stages
#define AOF_S   163840u           // fp32 [64][68]
#define AOF_PH  181248u           // bf16 [64][64] swizzled (8K)
#define AOF_PL  189440u
#define AOF_AL  197632u           // alpha[64] fp32
#define AOF_L   197888u           // l[64] fp32
#define ATTN_SMEM 198144

__global__ __launch_bounds__(256) void attn_mma(
    const bf16* __restrict__ Qh, const bf16* __restrict__ Ql,
    const bf16* __restrict__ Kh, const bf16* __restrict__ Kl,
    const bf16* __restrict__ Vh, const bf16* __restrict__ Vl,
    const float* __restrict__ qmask, const float* __restrict__ kvmask,
    bf16* __restrict__ Oh, bf16* __restrict__ Ol) {
    extern __shared__ __align__(1024) char smem[];
    uint32_t sb = s2u(smem);
    float* Ss = (float*)(smem + AOF_S);
    float* alpha_sm = (float*)(smem + AOF_AL);
    float* l_sm = (float*)(smem + AOF_L);

    const int qt = blockIdx.x, h = blockIdx.y, b = blockIdx.z;
    const int q0 = qt * 64;
    const int tid = threadIdx.x, wid = tid >> 5, lane = tid & 31;

    // S-phase warp layout: 2 (m) x 4 (n), warp tile 32x16
    const int sm_wm = (wid >> 2) * 32, sm_wn = (wid & 3) * 16;
    // PV-phase warp layout: 2 (m) x 4 (n over HD), warp tile 32x32
    const int pv_wm = (wid >> 2) * 32, pv_wn = (wid & 3) * 32;

    const int a_row = lane & 15, a_ch = lane >> 4;
    const int b_row = (lane & 7) + ((lane >> 4) & 1) * 8;
    const int b_ch  = (lane >> 3) & 1;
    const int cr = lane >> 2, cc = (lane & 3) * 2;

    // ---- load Q tile (group 0, together with KV stage 0) ----
    {
        #pragma unroll
        for (int i = 0; i < 4; i++) {
            int idx = tid + 256 * i;
            int r = idx >> 4, c16 = idx & 15;
            uint32_t off = r * 256 + (((uint32_t)(c16 ^ (r & 7))) << 4);
            size_t go = (size_t)(b * SQ_ + q0 + r) * D_ + h * HD_ + c16 * 8;
            cp16(sb + AOF_Q + off, Qh + go);
            cp16(sb + AOF_QL + off, Ql + go);
        }
    }
    auto kv_load = [&](int st, int t) {
        uint32_t s0 = sb + AOF_KV + st * 65536u;
        int kv0 = t * 64;
        #pragma unroll
        for (int i = 0; i < 4; i++) {
            int idx = tid + 256 * i;
            int r = idx >> 4, c16 = idx & 15;
            uint32_t off = r * 256 + (((uint32_t)(c16 ^ (r & 7))) << 4);
            size_t go = (size_t)(b * SKV_ + kv0 + r) * D_ + h * HD_ + c16 * 8;
            cp16(s0 + off,          Kh + go);
            cp16(s0 + 16384 + off,  Kl + go);
            cp16(s0 + 32768 + off,  Vh + go);
            cp16(s0 + 49152 + off,  Vl + go);
        }
        asm volatile("cp.async.commit_group;" ::: "memory");
    };
    kv_load(0, 0);

    // softmax row ownership: 4 threads per row
    const int srow = tid >> 2, ssub = tid & 3;
    const float qmv = qmask[b * SQ_ + q0 + srow];
    float m_reg = -1e30f, l_reg = 0.f;

    // O accumulators: 2 m-frags x 4 n-frags
    float oacc[2][4][4];
    #pragma unroll
    for (int i = 0; i < 2; i++)
        #pragma unroll
        for (int j = 0; j < 4; j++)
            #pragma unroll
            for (int c = 0; c < 4; c++) oacc[i][j][c] = 0.f;

    const int T = SKV_ / 64;  // 40
    for (int t = 0; t < T; ++t) {
        if (t + 1 < T) kv_load((t + 1) & 1, t + 1);
        if (t + 1 < T) {
            asm volatile("cp.async.wait_group 1;" ::: "memory");
        } else {
            asm volatile("cp.async.wait_group 0;" ::: "memory");
        }
        __syncthreads();

        uint32_t s0 = sb + AOF_KV + (t & 1) * 65536u;
        uint32_t sKh = s0, sKl = s0 + 16384, sVh = s0 + 32768, sVl = s0 + 49152;

        // ---- S = Q @ K^T ----
        float sacc[2][2][4];
        #pragma unroll
        for (int i = 0; i < 2; i++)
            #pragma unroll
            for (int j = 0; j < 2; j++)
                #pragma unroll
                for (int c = 0; c < 4; c++) sacc[i][j][c] = 0.f;

        #pragma unroll
        for (int ks = 0; ks < 8; ks++) {
            uint32_t qh_f[2][4], ql_f[2][4], kh_f[2][2], kl_f[2][2];
            #pragma unroll
            for (int i = 0; i < 2; i++) {
                int row = sm_wm + i * 16 + a_row;
                int c16 = ks * 2 + a_ch;
                uint32_t off = row * 256 + (((uint32_t)(c16 ^ (row & 7))) << 4);
                LDSM4(qh_f[i][0], qh_f[i][1], qh_f[i][2], qh_f[i][3], sb + AOF_Q + off);
                LDSM4(ql_f[i][0], ql_f[i][1], ql_f[i][2], ql_f[i][3], sb + AOF_QL + off);
            }
            {
                int row = sm_wn + b_row;
                int c16 = ks * 2 + b_ch;
                uint32_t off = row * 256 + (((uint32_t)(c16 ^ (row & 7))) << 4);
                uint32_t r0, r1, r2, r3;
                LDSM4(r0, r1, r2, r3, sKh + off);
                kh_f[0][0] = r0; kh_f[0][1] = r1; kh_f[1][0] = r2; kh_f[1][1] = r3;
                LDSM4(r0, r1, r2, r3, sKl + off);
                kl_f[0][0] = r0; kl_f[0][1] = r1; kl_f[1][0] = r2; kl_f[1][1] = r3;
            }
            #pragma unroll
            for (int i = 0; i < 2; i++)
                #pragma unroll
                for (int j = 0; j < 2; j++) {
                    MMA16816(sacc[i][j], qh_f[i], kh_f[j]);
                    MMA16816(sacc[i][j], qh_f[i], kl_f[j]);
                    MMA16816(sacc[i][j], ql_f[i], kh_f[j]);
                }
        }
        // store S frags
        #pragma unroll
        for (int i = 0; i < 2; i++)
            #pragma unroll
            for (int j = 0; j < 2; j++) {
                int row0 = sm_wm + i * 16 + cr;
                int col = sm_wn + j * 8 + cc;
                *(float2*)&Ss[row0 * 68 + col] = make_float2(sacc[i][j][0], sacc[i][j][1]);
                *(float2*)&Ss[(row0 + 8) * 68 + col] = make_float2(sacc[i][j][2], sacc[i][j][3]);
            }
        __syncthreads();

        // ---- softmax (4 threads per row, 16 cols each) ----
        {
            int kv0 = t * 64;
            float sv[16];
            const float* srp = &Ss[srow * 68 + ssub * 16];
            #pragma unroll
            for (int c4 = 0; c4 < 4; c4++) {
                float4 v = *(const float4*)(srp + c4 * 4);
                sv[c4 * 4 + 0] = v.x; sv[c4 * 4 + 1] = v.y;
                sv[c4 * 4 + 2] = v.z; sv[c4 * 4 + 3] = v.w;
            }
            const float* kmp = kvmask + b * SKV_ + kv0 + ssub * 16;
            #pragma unroll
            for (int c4 = 0; c4 < 4; c4++) {
                float4 km = *(const float4*)(kmp + c4 * 4);
                if (qmv == 0.f || km.x == 0.f) sv[c4 * 4 + 0] = -3.0e38f;
                if (qmv == 0.f || km.y == 0.f) sv[c4 * 4 + 1] = -3.0e38f;
                if (qmv == 0.f || km.z == 0.f) sv[c4 * 4 + 2] = -3.0e38f;
                if (qmv == 0.f || km.w == 0.f) sv[c4 * 4 + 3] = -3.0e38f;
            }
            float mx = sv[0];
            #pragma unroll
            for (int c = 1; c < 16; c++) mx = fmaxf(mx, sv[c]);
            mx = fmaxf(mx, __shfl_xor_sync(0xffffffffu, mx, 1));
            mx = fmaxf(mx, __shfl_xor_sync(0xffffffffu, mx, 2));
            float m_new = fmaxf(m_reg, mx);
            float p[16], sum = 0.f;
            #pragma unroll
            for (int c = 0; c < 16; c++) { p[c] = __expf(sv[c] - m_new); sum += p[c]; }
            sum += __shfl_xor_sync(0xffffffffu, sum, 1);
            sum += __shfl_xor_sync(0xffffffffu, sum, 2);
            float alpha = __expf(m_reg - m_new);
            l_reg = l_reg * alpha + sum;
            m_reg = m_new;
            if (ssub == 0) alpha_sm[srow] = alpha;
            // write P hi/lo (swizzled A layout, rows 128B)
            #pragma unroll
            for (int g = 0; g < 2; g++) {
                int c16 = ssub * 2 + g;
                uint32_t off = srow * 128 + (((uint32_t)(c16 ^ (srow & 7))) << 4);
                #pragma unroll
                for (int qq = 0; qq < 4; qq++) {
                    float v0 = p[g * 8 + qq * 2], v1 = p[g * 8 + qq * 2 + 1];
                    bf16 h0, l0, h1, l1;
                    bsplit(v0, &h0, &l0);
                    bsplit(v1, &h1, &l1);
                    *(__nv_bfloat162*)(smem + AOF_PH + off + qq * 4) = __nv_bfloat162(h0, h1);
                    *(__nv_bfloat162*)(smem + AOF_PL + off + qq * 4) = __nv_bfloat162(l0, l1);
                }
            }
        }
        __syncthreads();

        // ---- rescale O, then O += P @ V ----
        {
            float al0[2], al1[2];
            #pragma unroll
            for (int i = 0; i < 2; i++) {
                al0[i] = alpha_sm[pv_wm + i * 16 + cr];
                al1[i] = alpha_sm[pv_wm + i * 16 + cr + 8];
            }
            #pragma unroll
            for (int i = 0; i < 2; i++)
                #pragma unroll
                for (int j = 0; j < 4; j++) {
                    oacc[i][j][0] *= al0[i]; oacc[i][j][1] *= al0[i];
                    oacc[i][j][2] *= al1[i]; oacc[i][j][3] *= al1[i];
                }
        }
        #pragma unroll
        for (int ks = 0; ks < 4; ks++) {
            uint32_t ph_f[2][4], pl_f[2][4], vh_f[4][2], vl_f[4][2];
            #pragma unroll
            for (int i = 0; i < 2; i++) {
                int row = pv_wm + i * 16 + a_row;
                int c16 = ks * 2 + a_ch;
                uint32_t off = row * 128 + (((uint32_t)(c16 ^ (row & 7))) << 4);
                LDSM4(ph_f[i][0], ph_f[i][1], ph_f[i][2], ph_f[i][3], sb + AOF_PH + off);
                LDSM4(pl_f[i][0], pl_f[i][1], pl_f[i][2], pl_f[i][3], sb + AOF_PL + off);
            }
            #pragma unroll
            for (int ng = 0; ng < 2; ng++) {
                int k_row = ks * 16 + (lane & 15);
                int c16v = (pv_wn >> 3) + ng * 2 + (lane >> 4);
                uint32_t off = k_row * 256 + (((uint32_t)(c16v ^ (k_row & 7))) << 4);
                uint32_t r0, r1, r2, r3;
                LDSM4T(r0, r1, r2, r3, sVh + off);
                vh_f[ng * 2][0] = r0; vh_f[ng * 2][1] = r1;
                vh_f[ng * 2 + 1][0] = r2; vh_f[ng * 2 + 1][1] = r3;
                LDSM4T(r0, r1, r2, r3, sVl + off);
                vl_f[ng * 2][0] = r0; vl_f[ng * 2][1] = r1;
                vl_f[ng * 2 + 1][0] = r2; vl_f[ng * 2 + 1][1] = r3;
            }
            #pragma unroll
            for (int i = 0; i < 2; i++)
                #pragma unroll
                for (int j = 0; j < 4; j++) {
                    MMA16816(oacc[i][j], ph_f[i], vh_f[j]);
                    MMA16816(oacc[i][j], ph_f[i], vl_f[j]);
                    MMA16816(oacc[i][j], pl_f[i], vh_f[j]);
                }
        }
        __syncthreads();
    }

    // final l
    if (ssub == 0) l_sm[srow] = l_reg;
    __syncthreads();

    // epilogue: O /= l, write bf16 hi/lo ctx
    #pragma unroll
    for (int i = 0; i < 2; i++) {
        float inv0 = 1.0f / l_sm[pv_wm + i * 16 + cr];
        float inv1 = 1.0f / l_sm[pv_wm + i * 16 + cr + 8];
        #pragma unroll
        for (int j = 0; j < 4; j++) {
            int gcol = h * HD_ + pv_wn + j * 8 + cc;
            #pragma unroll
            for (int half = 0; half < 2; half++) {
                int grow = q0 + pv_wm + i * 16 + cr + half * 8;
                float inv = half ? inv1 : inv0;
                float v0 = oacc[i][j][half * 2 + 0] * inv;
                float v1 = oacc[i][j][half * 2 + 1] * inv;
                size_t o = (size_t)(b * SQ_ + grow) * D_ + gcol;
                bf16 h0, l0, h1, l1;
                bsplit(v0, &h0, &l0);
                bsplit(v1, &h1, &l1);
                *(__nv_bfloat162*)(Oh + o) = __nv_bfloat162(h0, h1);
                *(__nv_bfloat162*)(Ol + o) = __nv_bfloat162(l0, l1);
            }
        }
    }
}

// ---------------- launcher ----------------
extern "C" void kernel_launch(void* const* d_in, const int* in_sizes, int n_in,
                              void* d_out, int out_size) {
    const float* x     = (const float*)d_in[0];
    const float* pkv   = (const float*)d_in[1];
    const float* skv   = (const float*)d_in[2];
    const float* mkv   = (const float*)d_in[3];
    const float* qmask = (const float*)d_in[4];
    const float* pmask = (const float*)d_in[5];
    const float* smask = (const float*)d_in[6];
    const float* mmask = (const float*)d_in[7];
    const float* rmsw  = (const float*)d_in[8];
    const float* Wq  = (const float*)d_in[9];   const float* bq  = (const float*)d_in[10];
    const float* Wkp = (const float*)d_in[11];  const float* bkp = (const float*)d_in[12];
    const float* Wvp = (const float*)d_in[13];  const float* bvp = (const float*)d_in[14];
    const float* Wks = (const float*)d_in[15];  const float* bks = (const float*)d_in[16];
    const float* Wvs = (const float*)d_in[17];  const float* bvs = (const float*)d_in[18];
    const float* Wkm = (const float*)d_in[19];  const float* bkm = (const float*)d_in[20];
    const float* Wvm = (const float*)d_in[21];  const float* bvm = (const float*)d_in[22];
    const float* Wo  = (const float*)d_in[23];  const float* bo  = (const float*)d_in[24];
    const float* lng = (const float*)d_in[25];  const float* lnb = (const float*)d_in[26];
    const float* W1  = (const float*)d_in[27];  const float* W2  = (const float*)d_in[28];
    const float* ga  = (const float*)d_in[29];  const float* gf  = (const float*)d_in[30];
    float* out = (float*)d_out;

    float *hh, *kvm;
    cudaGetSymbolAddress((void**)&hh,  g_h);
    cudaGetSymbolAddress((void**)&kvm, g_kvmask);

    bf16 *qnh,*qnl,*aph,*apl,*ash,*asl,*amh,*aml;
    bf16 *qh,*ql,*kh,*kl,*vh,*vl,*cxh,*cxl,*lnh,*lnl,*ffh,*ffl;
    cudaGetSymbolAddress((void**)&qnh, g_qn_h);  cudaGetSymbolAddress((void**)&qnl, g_qn_l);
    cudaGetSymbolAddress((void**)&aph, g_ap_h);  cudaGetSymbolAddress((void**)&apl, g_ap_l);
    cudaGetSymbolAddress((void**)&ash, g_as_h);  cudaGetSymbolAddress((void**)&asl, g_as_l);
    cudaGetSymbolAddress((void**)&amh, g_am_h);  cudaGetSymbolAddress((void**)&aml, g_am_l);
    cudaGetSymbolAddress((void**)&qh,  g_qh);    cudaGetSymbolAddress((void**)&ql,  g_ql);
    cudaGetSymbolAddress((void**)&kh,  g_kh);    cudaGetSymbolAddress((void**)&kl,  g_kl);
    cudaGetSymbolAddress((void**)&vh,  g_vh);    cudaGetSymbolAddress((void**)&vl,  g_vl);
    cudaGetSymbolAddress((void**)&cxh, g_cx_h);  cudaGetSymbolAddress((void**)&cxl, g_cx_l);
    cudaGetSymbolAddress((void**)&lnh, g_ln_h);  cudaGetSymbolAddress((void**)&lnl, g_ln_l);
    cudaGetSymbolAddress((void**)&ffh, g_ff_h);  cudaGetSymbolAddress((void**)&ffl, g_ff_l);

    bf16 *tWqh,*tWql,*tWkph,*tWkpl,*tWvph,*tWvpl,*tWksh,*tWksl,*tWvsh,*tWvsl;
    bf16 *tWkmh,*tWkml,*tWvmh,*tWvml,*tWoh,*tWol,*tW1h,*tW1l,*tW2h,*tW2l;
    cudaGetSymbolAddress((void**)&tWqh,  g_Wq_h);   cudaGetSymbolAddress((void**)&tWql,  g_Wq_l);
    cudaGetSymbolAddress((void**)&tWkph, g_Wkp_h);  cudaGetSymbolAddress((void**)&tWkpl, g_Wkp_l);
    cudaGetSymbolAddress((void**)&tWvph, g_Wvp_h);  cudaGetSymbolAddress((void**)&tWvpl, g_Wvp_l);
    cudaGetSymbolAddress((void**)&tWksh, g_Wks_h);  cudaGetSymbolAddress((void**)&tWksl, g_Wks_l);
    cudaGetSymbolAddress((void**)&tWvsh, g_Wvs_h);  cudaGetSymbolAddress((void**)&tWvsl, g_Wvs_l);
    cudaGetSymbolAddress((void**)&tWkmh, g_Wkm_h);  cudaGetSymbolAddress((void**)&tWkml, g_Wkm_l);
    cudaGetSymbolAddress((void**)&tWvmh, g_Wvm_h);  cudaGetSymbolAddress((void**)&tWvml, g_Wvm_l);
    cudaGetSymbolAddress((void**)&tWoh,  g_Wo_h);   cudaGetSymbolAddress((void**)&tWol,  g_Wo_l);
    cudaGetSymbolAddress((void**)&tW1h,  g_W1_h);   cudaGetSymbolAddress((void**)&tW1l,  g_W1_l);
    cudaGetSymbolAddress((void**)&tW2h,  g_W2_h);   cudaGetSymbolAddress((void**)&tW2l,  g_W2_l);

    cudaFuncSetAttribute(gemm_mma<0>, cudaFuncAttributeMaxDynamicSharedMemorySize, GEMM_SMEM);
    cudaFuncSetAttribute(gemm_mma<2>, cudaFuncAttributeMaxDynamicSharedMemorySize, GEMM_SMEM);
    cudaFuncSetAttribute(gemm_mma<3>, cudaFuncAttributeMaxDynamicSharedMemorySize, GEMM_SMEM);
    cudaFuncSetAttribute(gemm_mma<4>, cudaFuncAttributeMaxDynamicSharedMemorySize, GEMM_SMEM);
    cudaFuncSetAttribute(gemm_mma<5>, cudaFuncAttributeMaxDynamicSharedMemorySize, GEMM_SMEM);
    cudaFuncSetAttribute(attn_mma, cudaFuncAttributeMaxDynamicSharedMemorySize, ATTN_SMEM);

    dim3 tb(32, 8);

    // weight transpose+split
    wsplit_T<<<dim3(D_ / 32,     D_ / 32),     tb>>>(Wq,  tWqh,  tWql,  D_,     D_);
    wsplit_T<<<dim3(D_ / 32,     DP_ / 32),    tb>>>(Wkp, tWkph, tWkpl, DP_,    D_);
    wsplit_T<<<dim3(D_ / 32,     DP_ / 32),    tb>>>(Wvp, tWvph, tWvpl, DP_,    D_);
    wsplit_T<<<dim3(D_ / 32,     DS_ / 32),    tb>>>(Wks, tWksh, tWksl, DS_,    D_);
    wsplit_T<<<dim3(D_ / 32,     DS_ / 32),    tb>>>(Wvs, tWvsh, tWvsl, DS_,    D_);
    wsplit_T<<<dim3(D_ / 32,     DM_ / 32),    tb>>>(Wkm, tWkmh, tWkml, DM_,    D_);
    wsplit_T<<<dim3(D_ / 32,     DM_ / 32),    tb>>>(Wvm, tWvmh, tWvml, DM_,    D_);
    wsplit_T<<<dim3(D_ / 32,     D_ / 32),     tb>>>(Wo,  tWoh,  tWol,  D_,     D_);
    wsplit_T<<<dim3(INNER_ / 32, D_ / 32),     tb>>>(W1,  tW1h,  tW1l,  D_,     INNER_);
    wsplit_T<<<dim3(D_ / 32,     INNER_ / 32), tb>>>(W2,  tW2h,  tW2l,  INNER_, D_);

    // activation splits + mask concat
    rmsnorm_split<<<B_ * SQ_, 256>>>(x, rmsw, qnh, qnl);
    split_k<<<(B_ * SP_ * DP_ + 255) / 256, 256>>>(pkv, aph, apl, B_ * SP_ * DP_);
    split_k<<<(B_ * SS_ * DS_ + 255) / 256, 256>>>(skv, ash, asl, B_ * SS_ * DS_);
    split_k<<<(B_ * SM_ * DM_ + 255) / 256, 256>>>(mkv, amh, aml, B_ * SM_ * DM_);
    maskcat_k<<<(B_ * SKV_ + 255) / 256, 256>>>(pmask, smask, mmask, kvm);

    // projections -> bf16 hi/lo (EPI 5). Q: scale 0.25 folded; K/V remap to concat [B,SKV,D].
    gemm_mma<5><<<dim3(16, 16), 256, GEMM_SMEM>>>(qnh, qnl, tWqh, tWql, bq, nullptr, nullptr,
        nullptr, qh, ql, 2048, 2048, 2048, 0.25f, 10, 1024, 0);
    gemm_mma<5><<<dim3(16, 16), 256, GEMM_SMEM>>>(aph, apl, tWkph, tWkpl, bkp, nullptr, nullptr,
        nullptr, kh, kl, 2048, 2048, 1280, 1.f, 10, SKV_, 0);
    gemm_mma<5><<<dim3(16, 16), 256, GEMM_SMEM>>>(aph, apl, tWvph, tWvpl, bvp, nullptr, nullptr,
        nullptr, vh, vl, 2048, 2048, 1280, 1.f, 10, SKV_, 0);
    gemm_mma<5><<<dim3(16, 16), 256, GEMM_SMEM>>>(ash, asl, tWksh, tWksl, bks, nullptr, nullptr,
        nullptr, kh, kl, 2048, 2048, 1024, 1.f, 10, SKV_, SP_);
    gemm_mma<5><<<dim3(16, 16), 256, GEMM_SMEM>>>(ash, asl, tWvsh, tWvsl, bvs, nullptr, nullptr,
        nullptr, vh, vl, 2048, 2048, 1024, 1.f, 10, SKV_, SP_);
    gemm_mma<5><<<dim3(16, 8), 256, GEMM_SMEM>>>(amh, aml, tWkmh, tWkml, bkm, nullptr, nullptr,
        nullptr, kh, kl, 1024, 2048, 768, 1.f, 9, SKV_, SP_ + SS_);
    gemm_mma<5><<<dim3(16, 8), 256, GEMM_SMEM>>>(amh, aml, tWvmh, tWvml, bvm, nullptr, nullptr,
        nullptr, vh, vl, 1024, 2048, 768, 1.f, 9, SKV_, SP_ + SS_);

    // attention (tensor-core) -> ctx bf16 hi/lo
    attn_mma<<<dim3(16, 16, 2), 256, ATTN_SMEM>>>(qh, ql, kh, kl, vh, vl,
                                                  qmask, kvm, cxh, cxl);

    // h = x + tanh(ga)*(ctx@Wo + bo)
    gemm_mma<2><<<dim3(16, 16), 256, GEMM_SMEM>>>(cxh, cxl, tWoh, tWol, bo, x, ga,
        hh, nullptr, nullptr, 2048, 2048, 2048, 1.f, 0, 0, 0);

    // LayerNorm
    layernorm_split<<<B_ * SQ_, 256>>>(hh, lng, lnb, lnh, lnl);

    // FFW
    gemm_mma<3><<<dim3(64, 16), 256, GEMM_SMEM>>>(lnh, lnl, tW1h, tW1l, nullptr, nullptr, nullptr,
        nullptr, ffh, ffl, 2048, INNER_, 2048, 1.f, 0, 0, 0);
    gemm_mma<4><<<dim3(16, 16), 256, GEMM_SMEM>>>(ffh, ffl, tW2h, tW2l, nullptr, hh, gf,
        out, nullptr, nullptr, 2048, 2048, INNER_, 1.f, 0, 0, 0);
}

// round 5
// speedup vs baseline: 3.2387x; 1.0634x over previous
#include <cuda_runtime.h>
#include <cuda_bf16.h>
#include <math.h>
#include <stdint.h>

typedef __nv_bfloat16 bf16;

// ---------------- problem dims ----------------
#define B_    2
#define SQ_   1024
#define D_    2048
#define H_    16
#define HD_   128
#define SP_   1024
#define SS_   1024
#define SM_   512
#define SKV_  2560
#define DP_   1280
#define DS_   1024
#define DM_   768
#define INNER_ 8192

// ---------------- scratch (device globals; no allocations) ----------------
__device__ float g_h  [B_*SQ_*D_];
__device__ float g_kvmask[B_*SKV_];
// bf16 activation splits (hi/lo)
__device__ bf16 g_qn_h [B_*SQ_*D_];   __device__ bf16 g_qn_l [B_*SQ_*D_];
__device__ bf16 g_ap_h [B_*SP_*DP_];  __device__ bf16 g_ap_l [B_*SP_*DP_];
__device__ bf16 g_as_h [B_*SS_*DS_];  __device__ bf16 g_as_l [B_*SS_*DS_];
__device__ bf16 g_am_h [B_*SM_*DM_];  __device__ bf16 g_am_l [B_*SM_*DM_];
__device__ bf16 g_qh   [B_*SQ_*D_];   __device__ bf16 g_ql   [B_*SQ_*D_];
__device__ bf16 g_kh   [B_*SKV_*D_];  __device__ bf16 g_kl   [B_*SKV_*D_];
__device__ bf16 g_vh   [B_*SKV_*D_];  __device__ bf16 g_vl   [B_*SKV_*D_];
__device__ bf16 g_cx_h [B_*SQ_*D_];   __device__ bf16 g_cx_l [B_*SQ_*D_];
__device__ bf16 g_ln_h [B_*SQ_*D_];   __device__ bf16 g_ln_l [B_*SQ_*D_];
__device__ bf16 g_ff_h [B_*SQ_*INNER_]; __device__ bf16 g_ff_l [B_*SQ_*INNER_];
// bf16 transposed weight splits [N,K]
__device__ bf16 g_Wq_h [D_*D_];       __device__ bf16 g_Wq_l [D_*D_];
__device__ bf16 g_Wkp_h[D_*DP_];      __device__ bf16 g_Wkp_l[D_*DP_];
__device__ bf16 g_Wvp_h[D_*DP_];      __device__ bf16 g_Wvp_l[D_*DP_];
__device__ bf16 g_Wks_h[D_*DS_];      __device__ bf16 g_Wks_l[D_*DS_];
__device__ bf16 g_Wvs_h[D_*DS_];      __device__ bf16 g_Wvs_l[D_*DS_];
__device__ bf16 g_Wkm_h[D_*DM_];      __device__ bf16 g_Wkm_l[D_*DM_];
__device__ bf16 g_Wvm_h[D_*DM_];      __device__ bf16 g_Wvm_l[D_*DM_];
__device__ bf16 g_Wo_h [D_*D_];       __device__ bf16 g_Wo_l [D_*D_];
__device__ bf16 g_W1_h [INNER_*D_];   __device__ bf16 g_W1_l [INNER_*D_];
__device__ bf16 g_W2_h [D_*INNER_];   __device__ bf16 g_W2_l [D_*INNER_];

// ---------------- helpers ----------------
__device__ __forceinline__ uint32_t s2u(const void* p) {
    uint32_t a;
    asm("{ .reg .u64 t; cvta.to.shared.u64 t, %1; cvt.u32.u64 %0, t; }" : "=r"(a) : "l"(p));
    return a;
}
__device__ __forceinline__ void cp16(uint32_t s, const void* g) {
    asm volatile("cp.async.cg.shared.global [%0], [%1], 16;" :: "r"(s), "l"(g) : "memory");
}
#define LDSM4(r0, r1, r2, r3, addr) \
    asm volatile("ldmatrix.sync.aligned.m8n8.x4.shared.b16 {%0,%1,%2,%3}, [%4];" \
                 : "=r"(r0), "=r"(r1), "=r"(r2), "=r"(r3) : "r"(addr))
#define LDSM4T(r0, r1, r2, r3, addr) \
    asm volatile("ldmatrix.sync.aligned.m8n8.x4.trans.shared.b16 {%0,%1,%2,%3}, [%4];" \
                 : "=r"(r0), "=r"(r1), "=r"(r2), "=r"(r3) : "r"(addr))
#define MMA16816(d, a, b) \
    asm volatile("mma.sync.aligned.m16n8k16.row.col.f32.bf16.bf16.f32 " \
                 "{%0,%1,%2,%3},{%4,%5,%6,%7},{%8,%9},{%0,%1,%2,%3};" \
                 : "+f"((d)[0]), "+f"((d)[1]), "+f"((d)[2]), "+f"((d)[3]) \
                 : "r"((a)[0]), "r"((a)[1]), "r"((a)[2]), "r"((a)[3]), \
                   "r"((b)[0]), "r"((b)[1]))
#define MMA16816_2(d, a0, a1, b0, b1) \
    asm volatile("mma.sync.aligned.m16n8k16.row.col.f32.bf16.bf16.f32 " \
                 "{%0,%1,%2,%3},{%4,%5,%6,%7},{%8,%9},{%0,%1,%2,%3};" \
                 : "+f"((d)[0]), "+f"((d)[1]), "+f"((d)[2]), "+f"((d)[3]) \
                 : "r"(a0), "r"(a1), "r"((a)[2]), "r"((a)[3]), \
                   "r"(b0), "r"(b1))

__device__ __forceinline__ float gelu_f(float x) {
    return 0.5f * x * (1.0f + erff(x * 0.70710678118654752f));
}
__device__ __forceinline__ void bsplit(float v, bf16* h, bf16* l) {
    bf16 hh = __float2bfloat16(v);
    *h = hh;
    *l = __float2bfloat16(v - __bfloat162float(hh));
}
__device__ __forceinline__ uint32_t pack2h(float a, float b) {
    __nv_bfloat162 t(__float2bfloat16(a), __float2bfloat16(b));
    return *(uint32_t*)&t;
}

// ---------------- block reduce ----------------
__device__ __forceinline__ float blockReduceSum(float v) {
    __shared__ float sh[32];
    __syncthreads();
    int lane = threadIdx.x & 31, w = threadIdx.x >> 5;
    #pragma unroll
    for (int o = 16; o > 0; o >>= 1) v += __shfl_xor_sync(0xffffffffu, v, o);
    if (lane == 0) sh[w] = v;
    __syncthreads();
    float r = 0.f;
    if (threadIdx.x < (blockDim.x >> 5)) r = sh[threadIdx.x];
    if (w == 0) {
        #pragma unroll
        for (int o = 16; o > 0; o >>= 1) r += __shfl_xor_sync(0xffffffffu, r, o);
        if (lane == 0) sh[0] = r;
    }
    __syncthreads();
    return sh[0];
}

// ---------------- RMSNorm / LayerNorm / splits ----------------
__global__ __launch_bounds__(256) void rmsnorm_split(const float* __restrict__ x,
                                                     const float* __restrict__ w,
                                                     bf16* __restrict__ yh,
                                                     bf16* __restrict__ yl) {
    int row = blockIdx.x;
    const float* xr = x + (size_t)row * D_;
    float ss = 0.f;
    for (int t = threadIdx.x; t < D_; t += 256) { float v = xr[t]; ss += v * v; }
    ss = blockReduceSum(ss);
    float inv = rsqrtf(ss / (float)D_ + 1e-6f);
    for (int t = threadIdx.x; t < D_; t += 256) {
        float v = xr[t] * inv * w[t];
        bsplit(v, yh + (size_t)row * D_ + t, yl + (size_t)row * D_ + t);
    }
}

__global__ __launch_bounds__(256) void layernorm_split(const float* __restrict__ x,
                                                       const float* __restrict__ gg,
                                                       const float* __restrict__ bb,
                                                       bf16* __restrict__ yh,
                                                       bf16* __restrict__ yl) {
    int row = blockIdx.x;
    const float* xr = x + (size_t)row * D_;
    float s = 0.f;
    for (int t = threadIdx.x; t < D_; t += 256) s += xr[t];
    s = blockReduceSum(s);
    float mu = s / (float)D_;
    float vs = 0.f;
    for (int t = threadIdx.x; t < D_; t += 256) { float d = xr[t] - mu; vs += d * d; }
    vs = blockReduceSum(vs);
    float inv = rsqrtf(vs / (float)D_ + 1e-5f);
    for (int t = threadIdx.x; t < D_; t += 256) {
        float v = (xr[t] - mu) * inv * gg[t] + bb[t];
        bsplit(v, yh + (size_t)row * D_ + t, yl + (size_t)row * D_ + t);
    }
}

__global__ __launch_bounds__(256) void split_k(const float* __restrict__ x,
                                               bf16* __restrict__ h,
                                               bf16* __restrict__ l, int n) {
    int i = blockIdx.x * 256 + threadIdx.x;
    if (i < n) { bsplit(x[i], h + i, l + i); }
}

__global__ __launch_bounds__(256) void maskcat_k(const float* __restrict__ pm,
                                                 const float* __restrict__ sm,
                                                 const float* __restrict__ mm,
                                                 float* __restrict__ out) {
    int i = blockIdx.x * 256 + threadIdx.x;
    if (i >= B_ * SKV_) return;
    int b = i / SKV_, s = i % SKV_;
    float v;
    if (s < SP_) v = pm[b * SP_ + s];
    else if (s < SP_ + SS_) v = sm[b * SS_ + s - SP_];
    else v = mm[b * SM_ + s - SP_ - SS_];
    out[i] = v;
}

// ---------------- weight transpose+split: W[K,N] -> T[N,K] hi/lo ----------------
__global__ __launch_bounds__(256) void wsplit_T(const float* __restrict__ W,
                                                bf16* __restrict__ Th,
                                                bf16* __restrict__ Tl,
                                                int K, int N) {
    __shared__ float tile[32][33];
    int n0 = blockIdx.x * 32, k0 = blockIdx.y * 32;
    int tx = threadIdx.x, ty = threadIdx.y;
    #pragma unroll
    for (int i = ty; i < 32; i += 8)
        tile[i][tx] = W[(size_t)(k0 + i) * N + n0 + tx];
    __syncthreads();
    #pragma unroll
    for (int i = ty; i < 32; i += 8) {
        float v = tile[tx][i];
        size_t o = (size_t)(n0 + i) * K + k0 + tx;
        bsplit(v, Th + o, Tl + o);
    }
}

// ---------------- mma.sync GEMM: C[M,N] = A[M,K] @ T[N,K]^T (3-term bf16) ----------------
#define GB_M 128
#define GB_N 128
#define GB_K 64
#define STAGE_BYTES 65536
#define GEMM_SMEM (2 * STAGE_BYTES)

template <int EPI>
__global__ __launch_bounds__(256) void gemm_mma(
    const bf16* __restrict__ Ah, const bf16* __restrict__ Al,
    const bf16* __restrict__ Bh, const bf16* __restrict__ Bl,
    const float* __restrict__ bias, const float* __restrict__ res,
    const float* __restrict__ gate,
    float* __restrict__ Cf, bf16* __restrict__ Ch, bf16* __restrict__ Cl,
    int M, int N, int K, float scale, int oShift, int oStride, int oOff) {
    extern __shared__ __align__(1024) char smem[];
    uint32_t sb = s2u(smem);
    const int tid = threadIdx.x, wid = tid >> 5, lane = tid & 31;
    const int n0 = blockIdx.x * GB_N, m0 = blockIdx.y * GB_M;
    const int wm0 = (wid >> 2) * 64;
    const int wn0 = (wid & 3) * 32;

    auto stage_load = [&](int st, int k0) {
        uint32_t s0 = sb + st * STAGE_BYTES;
        #pragma unroll
        for (int i = 0; i < 4; i++) {
            int idx = tid + 256 * i;
            int r = idx >> 3, c = idx & 7;
            uint32_t byte = r * 128 + c * 16;
            uint32_t sw = byte ^ ((byte >> 3) & 0x70);
            size_t goA = (size_t)(m0 + r) * K + k0 + c * 8;
            size_t goB = (size_t)(n0 + r) * K + k0 + c * 8;
            cp16(s0 + sw,         Ah + goA);
            cp16(s0 + 16384 + sw, Al + goA);
            cp16(s0 + 32768 + sw, Bh + goB);
            cp16(s0 + 49152 + sw, Bl + goB);
        }
        asm volatile("cp.async.commit_group;" ::: "memory");
    };

    float acc[4][4][4];
    #pragma unroll
    for (int i = 0; i < 4; i++)
        #pragma unroll
        for (int j = 0; j < 4; j++)
            #pragma unroll
            for (int c = 0; c < 4; c++) acc[i][j][c] = 0.f;

    const int nIter = K / GB_K;
    stage_load(0, 0);

    const int a_row = lane & 15;
    const int a_ch  = lane >> 4;
    const int b_row = (lane & 7) + ((lane >> 4) & 1) * 8;
    const int b_ch  = (lane >> 3) & 1;

    for (int it = 0; it < nIter; ++it) {
        if (it + 1 < nIter) stage_load((it + 1) & 1, (it + 1) * GB_K);
        if (it + 1 < nIter) {
            asm volatile("cp.async.wait_group 1;" ::: "memory");
        } else {
            asm volatile("cp.async.wait_group 0;" ::: "memory");
        }
        __syncthreads();

        uint32_t s0 = sb + (it & 1) * STAGE_BYTES;
        uint32_t sAh = s0, sAl = s0 + 16384, sBh = s0 + 32768, sBl = s0 + 49152;

        #pragma unroll
        for (int ks = 0; ks < 4; ks++) {
            uint32_t ahi[4][4], alo[4][4], bhi[4][2], blo[4][2];
            #pragma unroll
            for (int i = 0; i < 4; i++) {
                uint32_t byte = (wm0 + i * 16 + a_row) * 128 + (ks * 2 + a_ch) * 16;
                uint32_t sw = byte ^ ((byte >> 3) & 0x70);
                LDSM4(ahi[i][0], ahi[i][1], ahi[i][2], ahi[i][3], sAh + sw);
                LDSM4(alo[i][0], alo[i][1], alo[i][2], alo[i][3], sAl + sw);
            }
            #pragma unroll
            for (int jj = 0; jj < 2; jj++) {
                uint32_t byte = (wn0 + jj * 16 + b_row) * 128 + (ks * 2 + b_ch) * 16;
                uint32_t sw = byte ^ ((byte >> 3) & 0x70);
                uint32_t r0, r1, r2, r3;
                LDSM4(r0, r1, r2, r3, sBh + sw);
                bhi[jj * 2][0] = r0; bhi[jj * 2][1] = r1;
                bhi[jj * 2 + 1][0] = r2; bhi[jj * 2 + 1][1] = r3;
                LDSM4(r0, r1, r2, r3, sBl + sw);
                blo[jj * 2][0] = r0; blo[jj * 2][1] = r1;
                blo[jj * 2 + 1][0] = r2; blo[jj * 2 + 1][1] = r3;
            }
            #pragma unroll
            for (int i = 0; i < 4; i++)
                #pragma unroll
                for (int j = 0; j < 4; j++) {
                    MMA16816(acc[i][j], ahi[i], bhi[j]);
                    MMA16816(acc[i][j], ahi[i], blo[j]);
                    MMA16816(acc[i][j], alo[i], bhi[j]);
                }
        }
        __syncthreads();
    }

    float gt = 0.f;
    if (EPI == 2 || EPI == 4) gt = tanhf(gate[0]);
    const int cr = lane >> 2;
    const int cc = (lane & 3) * 2;

    #pragma unroll
    for (int i = 0; i < 4; i++) {
        #pragma unroll
        for (int j = 0; j < 4; j++) {
            int gcol = n0 + wn0 + j * 8 + cc;
            #pragma unroll
            for (int half = 0; half < 2; half++) {
                int grow = m0 + wm0 + i * 16 + cr + half * 8;
                float v0 = acc[i][j][half * 2 + 0];
                float v1 = acc[i][j][half * 2 + 1];
                size_t o = (size_t)grow * N + gcol;
                if (EPI == 0) {
                    *(float2*)(Cf + o) = make_float2(v0 + bias[gcol], v1 + bias[gcol + 1]);
                } else if (EPI == 2) {
                    float2 rr = *(const float2*)(res + o);
                    *(float2*)(Cf + o) = make_float2(rr.x + gt * (v0 + bias[gcol]),
                                                     rr.y + gt * (v1 + bias[gcol + 1]));
                } else if (EPI == 3) {
                    float a0 = gelu_f(v0), a1 = gelu_f(v1);
                    bf16 h0, l0, h1, l1;
                    bsplit(a0, &h0, &l0);
                    bsplit(a1, &h1, &l1);
                    *(__nv_bfloat162*)(Ch + o) = __nv_bfloat162(h0, h1);
                    *(__nv_bfloat162*)(Cl + o) = __nv_bfloat162(l0, l1);
                } else if (EPI == 4) {
                    float2 rr = *(const float2*)(res + o);
                    *(float2*)(Cf + o) = make_float2(rr.x + gt * v0, rr.y + gt * v1);
                } else {  // EPI 5
                    int ib = grow >> oShift;
                    int ir = grow & ((1 << oShift) - 1);
                    size_t oo = ((size_t)ib * oStride + oOff + ir) * N + gcol;
                    float a0 = (v0 + bias[gcol]) * scale;
                    float a1 = (v1 + bias[gcol + 1]) * scale;
                    bf16 h0, l0, h1, l1;
                    bsplit(a0, &h0, &l0);
                    bsplit(a1, &h1, &l1);
                    *(__nv_bfloat162*)(Ch + oo) = __nv_bfloat162(h0, h1);
                    *(__nv_bfloat162*)(Cl + oo) = __nv_bfloat162(l0, l1);
                }
            }
        }
    }
}

// ---------------- register-resident FA2 attention ----------------
// BQ=128, BKV=64, 256 threads / 8 warps; warp w owns rows w*16..w*16+15.
// smem: Q hi 32K | Q lo 32K | 2 stages x (Kh 16K | Kl 16K | Vh 16K | Vl 16K | mask 256B)
#define AQ_H 0u
#define AQ_L 32768u
#define AKV  65536u
#define AST  65792u              // per-stage stride
#define ATTN_SMEM (65536 + 2 * 65792)

__global__ __launch_bounds__(256) void attn_fa2(
    const bf16* __restrict__ Qh, const bf16* __restrict__ Ql,
    const bf16* __restrict__ Kh, const bf16* __restrict__ Kl,
    const bf16* __restrict__ Vh, const bf16* __restrict__ Vl,
    const float* __restrict__ qmask, const float* __restrict__ kvmask,
    bf16* __restrict__ Oh, bf16* __restrict__ Ol) {
    extern __shared__ __align__(1024) char smem[];
    uint32_t sb = s2u(smem);

    const int qt = blockIdx.x, h = blockIdx.y, b = blockIdx.z;
    const int q0 = qt * 128;
    const int tid = threadIdx.x, wid = tid >> 5, lane = tid & 31;
    const int wrow = wid * 16;
    const int a_row = lane & 15, a_ch = lane >> 4;
    const int b_row = (lane & 7) + ((lane >> 4) & 1) * 8;
    const int b_ch  = (lane >> 3) & 1;
    const int cr = lane >> 2, cc = (lane & 3) * 2;

    // ---- stage loaders ----
    auto kv_load = [&](int st, int t) {
        uint32_t s0 = sb + AKV + st * AST;
        int kv0 = t * 64;
        #pragma unroll
        for (int i = 0; i < 4; i++) {
            int idx = tid + 256 * i;       // 1024 chunks: 64 rows x 16 c16
            int r = idx >> 4, c16 = idx & 15;
            uint32_t off = r * 256 + (((uint32_t)(c16 ^ (r & 7))) << 4);
            size_t go = (size_t)(b * SKV_ + kv0 + r) * D_ + h * HD_ + c16 * 8;
            cp16(s0 + off,          Kh + go);
            cp16(s0 + 16384 + off,  Kl + go);
            cp16(s0 + 32768 + off,  Vh + go);
            cp16(s0 + 49152 + off,  Vl + go);
        }
        if (tid < 16)
            cp16(s0 + 65536 + tid * 16, kvmask + b * SKV_ + t * 64 + tid * 4);
        asm volatile("cp.async.commit_group;" ::: "memory");
    };

    // Q tile load (its own group), then KV stage 0
    #pragma unroll
    for (int i = 0; i < 8; i++) {
        int idx = tid + 256 * i;           // 2048 chunks: 128 rows x 16 c16
        int r = idx >> 4, c16 = idx & 15;
        uint32_t off = r * 256 + (((uint32_t)(c16 ^ (r & 7))) << 4);
        size_t go = (size_t)(b * SQ_ + q0 + r) * D_ + h * HD_ + c16 * 8;
        cp16(sb + AQ_H + off, Qh + go);
        cp16(sb + AQ_L + off, Ql + go);
    }
    asm volatile("cp.async.commit_group;" ::: "memory");
    kv_load(0, 0);
    asm volatile("cp.async.wait_group 0;" ::: "memory");
    __syncthreads();

    // ---- Q fragments resident in registers ----
    uint32_t qhf[8][4], qlf[8][4];
    #pragma unroll
    for (int ks = 0; ks < 8; ks++) {
        int row = wrow + a_row;
        int c16 = ks * 2 + a_ch;
        uint32_t off = row * 256 + (((uint32_t)(c16 ^ (row & 7))) << 4);
        LDSM4(qhf[ks][0], qhf[ks][1], qhf[ks][2], qhf[ks][3], sb + AQ_H + off);
        LDSM4(qlf[ks][0], qlf[ks][1], qlf[ks][2], qlf[ks][3], sb + AQ_L + off);
    }

    const float qm0 = qmask[b * SQ_ + q0 + wrow + cr];
    const float qm8 = qmask[b * SQ_ + q0 + wrow + cr + 8];

    float m0 = -1e30f, m8 = -1e30f, l0 = 0.f, l8 = 0.f;
    float oacc[16][4];
    #pragma unroll
    for (int j = 0; j < 16; j++)
        #pragma unroll
        for (int c = 0; c < 4; c++) oacc[j][c] = 0.f;

    const int T = SKV_ / 64;
    for (int t = 0; t < T; ++t) {
        if (t + 1 < T) kv_load((t + 1) & 1, t + 1);
        if (t + 1 < T) {
            asm volatile("cp.async.wait_group 1;" ::: "memory");
        } else {
            asm volatile("cp.async.wait_group 0;" ::: "memory");
        }
        __syncthreads();

        uint32_t s0 = sb + AKV + (t & 1) * AST;
        uint32_t sKh = s0, sKl = s0 + 16384, sVh = s0 + 32768, sVl = s0 + 49152;
        const float* msk = (const float*)(smem + AKV + (t & 1) * AST + 65536);

        // ---- S = Q @ K^T (rows: warp's 16, cols: 64 kv) ----
        float sacc[8][4];
        #pragma unroll
        for (int j = 0; j < 8; j++)
            #pragma unroll
            for (int c = 0; c < 4; c++) sacc[j][c] = 0.f;

        #pragma unroll
        for (int ks = 0; ks < 8; ks++) {
            #pragma unroll
            for (int jj = 0; jj < 4; jj++) {
                int row = jj * 16 + b_row;
                int c16 = ks * 2 + b_ch;
                uint32_t off = row * 256 + (((uint32_t)(c16 ^ (row & 7))) << 4);
                uint32_t k0, k1, k2, k3, e0, e1, e2, e3;
                LDSM4(k0, k1, k2, k3, sKh + off);
                LDSM4(e0, e1, e2, e3, sKl + off);
                uint32_t bh0[2] = {k0, k1}, bh1[2] = {k2, k3};
                uint32_t bl0[2] = {e0, e1}, bl1[2] = {e2, e3};
                MMA16816(sacc[jj * 2],     qhf[ks], bh0);
                MMA16816(sacc[jj * 2],     qhf[ks], bl0);
                MMA16816(sacc[jj * 2],     qlf[ks], bh0);
                MMA16816(sacc[jj * 2 + 1], qhf[ks], bh1);
                MMA16816(sacc[jj * 2 + 1], qhf[ks], bl1);
                MMA16816(sacc[jj * 2 + 1], qlf[ks], bh1);
            }
        }

        // ---- mask + online softmax, fully in registers ----
        #pragma unroll
        for (int j = 0; j < 8; j++) {
            float2 km = *(const float2*)&msk[j * 8 + cc];
            if (qm0 == 0.f || km.x == 0.f) sacc[j][0] = -3.0e38f;
            if (qm0 == 0.f || km.y == 0.f) sacc[j][1] = -3.0e38f;
            if (qm8 == 0.f || km.x == 0.f) sacc[j][2] = -3.0e38f;
            if (qm8 == 0.f || km.y == 0.f) sacc[j][3] = -3.0e38f;
        }
        float mx0 = sacc[0][0], mx8 = sacc[0][2];
        #pragma unroll
        for (int j = 0; j < 8; j++) {
            mx0 = fmaxf(mx0, fmaxf(sacc[j][0], sacc[j][1]));
            mx8 = fmaxf(mx8, fmaxf(sacc[j][2], sacc[j][3]));
        }
        mx0 = fmaxf(mx0, __shfl_xor_sync(0xffffffffu, mx0, 1));
        mx0 = fmaxf(mx0, __shfl_xor_sync(0xffffffffu, mx0, 2));
        mx8 = fmaxf(mx8, __shfl_xor_sync(0xffffffffu, mx8, 1));
        mx8 = fmaxf(mx8, __shfl_xor_sync(0xffffffffu, mx8, 2));
        float m0n = fmaxf(m0, mx0), m8n = fmaxf(m8, mx8);
        float al0 = __expf(m0 - m0n), al8 = __expf(m8 - m8n);
        float sum0 = 0.f, sum8 = 0.f;
        #pragma unroll
        for (int j = 0; j < 8; j++) {
            sacc[j][0] = __expf(sacc[j][0] - m0n);
            sacc[j][1] = __expf(sacc[j][1] - m0n);
            sacc[j][2] = __expf(sacc[j][2] - m8n);
            sacc[j][3] = __expf(sacc[j][3] - m8n);
            sum0 += sacc[j][0] + sacc[j][1];
            sum8 += sacc[j][2] + sacc[j][3];
        }
        sum0 += __shfl_xor_sync(0xffffffffu, sum0, 1);
        sum0 += __shfl_xor_sync(0xffffffffu, sum0, 2);
        sum8 += __shfl_xor_sync(0xffffffffu, sum8, 1);
        sum8 += __shfl_xor_sync(0xffffffffu, sum8, 2);
        l0 = l0 * al0 + sum0; l8 = l8 * al8 + sum8;
        m0 = m0n; m8 = m8n;

        // rescale O
        #pragma unroll
        for (int j = 0; j < 16; j++) {
            oacc[j][0] *= al0; oacc[j][1] *= al0;
            oacc[j][2] *= al8; oacc[j][3] *= al8;
        }

        // ---- O += P @ V  (P fragments built in registers from sacc) ----
        #pragma unroll
        for (int ks = 0; ks < 4; ks++) {
            // split P to bf16 hi/lo A-frags
            uint32_t ph[4], pl[4];
            {
                float v00 = sacc[ks * 2][0],     v01 = sacc[ks * 2][1];
                float v02 = sacc[ks * 2][2],     v03 = sacc[ks * 2][3];
                float v10 = sacc[ks * 2 + 1][0], v11 = sacc[ks * 2 + 1][1];
                float v12 = sacc[ks * 2 + 1][2], v13 = sacc[ks * 2 + 1][3];
                ph[0] = pack2h(v00, v01); ph[1] = pack2h(v02, v03);
                ph[2] = pack2h(v10, v11); ph[3] = pack2h(v12, v13);
                __nv_bfloat162 h0 = *(__nv_bfloat162*)&ph[0];
                __nv_bfloat162 h1 = *(__nv_bfloat162*)&ph[1];
                __nv_bfloat162 h2 = *(__nv_bfloat162*)&ph[2];
                __nv_bfloat162 h3 = *(__nv_bfloat162*)&ph[3];
                pl[0] = pack2h(v00 - __bfloat162float(h0.x), v01 - __bfloat162float(h0.y));
                pl[1] = pack2h(v02 - __bfloat162float(h1.x), v03 - __bfloat162float(h1.y));
                pl[2] = pack2h(v10 - __bfloat162float(h2.x), v11 - __bfloat162float(h2.y));
                pl[3] = pack2h(v12 - __bfloat162float(h3.x), v13 - __bfloat162float(h3.y));
            }
            #pragma unroll
            for (int ng = 0; ng < 8; ng++) {
                int k_row = ks * 16 + (lane & 15);
                int c16v = ng * 2 + (lane >> 4);
                uint32_t off = k_row * 256 + (((uint32_t)(c16v ^ (k_row & 7))) << 4);
                uint32_t v0, v1, v2, v3, w0, w1, w2, w3;
                LDSM4T(v0, v1, v2, v3, sVh + off);
                LDSM4T(w0, w1, w2, w3, sVl + off);
                uint32_t bh0[2] = {v0, v1}, bh1[2] = {v2, v3};
                uint32_t bl0[2] = {w0, w1}, bl1[2] = {w2, w3};
                MMA16816(oacc[ng * 2],     ph, bh0);
                MMA16816(oacc[ng * 2],     ph, bl0);
                MMA16816(oacc[ng * 2],     pl, bh0);
                MMA16816(oacc[ng * 2 + 1], ph, bh1);
                MMA16816(oacc[ng * 2 + 1], ph, bl1);
                MMA16816(oacc[ng * 2 + 1], pl, bh1);
            }
        }
        __syncthreads();
    }

    // ---- epilogue: O /= l, write bf16 hi/lo ctx ----
    float inv0 = 1.0f / l0, inv8 = 1.0f / l8;
    #pragma unroll
    for (int j = 0; j < 16; j++) {
        int gcol = h * HD_ + j * 8 + cc;
        int r0 = q0 + wrow + cr;
        size_t o0 = (size_t)(b * SQ_ + r0) * D_ + gcol;
        size_t o8 = o0 + (size_t)8 * D_;
        float a0 = oacc[j][0] * inv0, a1 = oacc[j][1] * inv0;
        float a2 = oacc[j][2] * inv8, a3 = oacc[j][3] * inv8;
        bf16 h0, l0b, h1, l1b;
        bsplit(a0, &h0, &l0b); bsplit(a1, &h1, &l1b);
        *(__nv_bfloat162*)(Oh + o0) = __nv_bfloat162(h0, h1);
        *(__nv_bfloat162*)(Ol + o0) = __nv_bfloat162(l0b, l1b);
        bsplit(a2, &h0, &l0b); bsplit(a3, &h1, &l1b);
        *(__nv_bfloat162*)(Oh + o8) = __nv_bfloat162(h0, h1);
        *(__nv_bfloat162*)(Ol + o8) = __nv_bfloat162(l0b, l1b);
    }
}

// ---------------- launcher ----------------
extern "C" void kernel_launch(void* const* d_in, const int* in_sizes, int n_in,
                              void* d_out, int out_size) {
    const float* x     = (const float*)d_in[0];
    const float* pkv   = (const float*)d_in[1];
    const float* skv   = (const float*)d_in[2];
    const float* mkv   = (const float*)d_in[3];
    const float* qmask = (const float*)d_in[4];
    const float* pmask = (const float*)d_in[5];
    const float* smask = (const float*)d_in[6];
    const float* mmask = (const float*)d_in[7];
    const float* rmsw  = (const float*)d_in[8];
    const float* Wq  = (const float*)d_in[9];   const float* bq  = (const float*)d_in[10];
    const float* Wkp = (const float*)d_in[11];  const float* bkp = (const float*)d_in[12];
    const float* Wvp = (const float*)d_in[13];  const float* bvp = (const float*)d_in[14];
    const float* Wks = (const float*)d_in[15];  const float* bks = (const float*)d_in[16];
    const float* Wvs = (const float*)d_in[17];  const float* bvs = (const float*)d_in[18];
    const float* Wkm = (const float*)d_in[19];  const float* bkm = (const float*)d_in[20];
    const float* Wvm = (const float*)d_in[21];  const float* bvm = (const float*)d_in[22];
    const float* Wo  = (const float*)d_in[23];  const float* bo  = (const float*)d_in[24];
    const float* lng = (const float*)d_in[25];  const float* lnb = (const float*)d_in[26];
    const float* W1  = (const float*)d_in[27];  const float* W2  = (const float*)d_in[28];
    const float* ga  = (const float*)d_in[29];  const float* gf  = (const float*)d_in[30];
    float* out = (float*)d_out;

    float *hh, *kvm;
    cudaGetSymbolAddress((void**)&hh,  g_h);
    cudaGetSymbolAddress((void**)&kvm, g_kvmask);

    bf16 *qnh,*qnl,*aph,*apl,*ash,*asl,*amh,*aml;
    bf16 *qh,*ql,*kh,*kl,*vh,*vl,*cxh,*cxl,*lnh,*lnl,*ffh,*ffl;
    cudaGetSymbolAddress((void**)&qnh, g_qn_h);  cudaGetSymbolAddress((void**)&qnl, g_qn_l);
    cudaGetSymbolAddress((void**)&aph, g_ap_h);  cudaGetSymbolAddress((void**)&apl, g_ap_l);
    cudaGetSymbolAddress((void**)&ash, g_as_h);  cudaGetSymbolAddress((void**)&asl, g_as_l);
    cudaGetSymbolAddress((void**)&amh, g_am_h);  cudaGetSymbolAddress((void**)&aml, g_am_l);
    cudaGetSymbolAddress((void**)&qh,  g_qh);    cudaGetSymbolAddress((void**)&ql,  g_ql);
    cudaGetSymbolAddress((void**)&kh,  g_kh);    cudaGetSymbolAddress((void**)&kl,  g_kl);
    cudaGetSymbolAddress((void**)&vh,  g_vh);    cudaGetSymbolAddress((void**)&vl,  g_vl);
    cudaGetSymbolAddress((void**)&cxh, g_cx_h);  cudaGetSymbolAddress((void**)&cxl, g_cx_l);
    cudaGetSymbolAddress((void**)&lnh, g_ln_h);  cudaGetSymbolAddress((void**)&lnl, g_ln_l);
    cudaGetSymbolAddress((void**)&ffh, g_ff_h);  cudaGetSymbolAddress((void**)&ffl, g_ff_l);

    bf16 *tWqh,*tWql,*tWkph,*tWkpl,*tWvph,*tWvpl,*tWksh,*tWksl,*tWvsh,*tWvsl;
    bf16 *tWkmh,*tWkml,*tWvmh,*tWvml,*tWoh,*tWol,*tW1h,*tW1l,*tW2h,*tW2l;
    cudaGetSymbolAddress((void**)&tWqh,  g_Wq_h);   cudaGetSymbolAddress((void**)&tWql,  g_Wq_l);
    cudaGetSymbolAddress((void**)&tWkph, g_Wkp_h);  cudaGetSymbolAddress((void**)&tWkpl, g_Wkp_l);
    cudaGetSymbolAddress((void**)&tWvph, g_Wvp_h);  cudaGetSymbolAddress((void**)&tWvpl, g_Wvp_l);
    cudaGetSymbolAddress((void**)&tWksh, g_Wks_h);  cudaGetSymbolAddress((void**)&tWksl, g_Wks_l);
    cudaGetSymbolAddress((void**)&tWvsh, g_Wvs_h);  cudaGetSymbolAddress((void**)&tWvsl, g_Wvs_l);
    cudaGetSymbolAddress((void**)&tWkmh, g_Wkm_h);  cudaGetSymbolAddress((void**)&tWkml, g_Wkm_l);
    cudaGetSymbolAddress((void**)&tWvmh, g_Wvm_h);  cudaGetSymbolAddress((void**)&tWvml, g_Wvm_l);
    cudaGetSymbolAddress((void**)&tWoh,  g_Wo_h);   cudaGetSymbolAddress((void**)&tWol,  g_Wo_l);
    cudaGetSymbolAddress((void**)&tW1h,  g_W1_h);   cudaGetSymbolAddress((void**)&tW1l,  g_W1_l);
    cudaGetSymbolAddress((void**)&tW2h,  g_W2_h);   cudaGetSymbolAddress((void**)&tW2l,  g_W2_l);

    cudaFuncSetAttribute(gemm_mma<0>, cudaFuncAttributeMaxDynamicSharedMemorySize, GEMM_SMEM);
    cudaFuncSetAttribute(gemm_mma<2>, cudaFuncAttributeMaxDynamicSharedMemorySize, GEMM_SMEM);
    cudaFuncSetAttribute(gemm_mma<3>, cudaFuncAttributeMaxDynamicSharedMemorySize, GEMM_SMEM);
    cudaFuncSetAttribute(gemm_mma<4>, cudaFuncAttributeMaxDynamicSharedMemorySize, GEMM_SMEM);
    cudaFuncSetAttribute(gemm_mma<5>, cudaFuncAttributeMaxDynamicSharedMemorySize, GEMM_SMEM);
    cudaFuncSetAttribute(attn_fa2, cudaFuncAttributeMaxDynamicSharedMemorySize, ATTN_SMEM);

    dim3 tb(32, 8);

    // weight transpose+split
    wsplit_T<<<dim3(D_ / 32,     D_ / 32),     tb>>>(Wq,  tWqh,  tWql,  D_,     D_);
    wsplit_T<<<dim3(D_ / 32,     DP_ / 32),    tb>>>(Wkp, tWkph, tWkpl, DP_,    D_);
    wsplit_T<<<dim3(D_ / 32,     DP_ / 32),    tb>>>(Wvp, tWvph, tWvpl, DP_,    D_);
    wsplit_T<<<dim3(D_ / 32,     DS_ / 32),    tb>>>(Wks, tWksh, tWksl, DS_,    D_);
    wsplit_T<<<dim3(D_ / 32,     DS_ / 32),    tb>>>(Wvs, tWvsh, tWvsl, DS_,    D_);
    wsplit_T<<<dim3(D_ / 32,     DM_ / 32),    tb>>>(Wkm, tWkmh, tWkml, DM_,    D_);
    wsplit_T<<<dim3(D_ / 32,     DM_ / 32),    tb>>>(Wvm, tWvmh, tWvml, DM_,    D_);
    wsplit_T<<<dim3(D_ / 32,     D_ / 32),     tb>>>(Wo,  tWoh,  tWol,  D_,     D_);
    wsplit_T<<<dim3(INNER_ / 32, D_ / 32),     tb>>>(W1,  tW1h,  tW1l,  D_,     INNER_);
    wsplit_T<<<dim3(D_ / 32,     INNER_ / 32), tb>>>(W2,  tW2h,  tW2l,  INNER_, D_);

    // activation splits + mask concat
    rmsnorm_split<<<B_ * SQ_, 256>>>(x, rmsw, qnh, qnl);
    split_k<<<(B_ * SP_ * DP_ + 255) / 256, 256>>>(pkv, aph, apl, B_ * SP_ * DP_);
    split_k<<<(B_ * SS_ * DS_ + 255) / 256, 256>>>(skv, ash, asl, B_ * SS_ * DS_);
    split_k<<<(B_ * SM_ * DM_ + 255) / 256, 256>>>(mkv, amh, aml, B_ * SM_ * DM_);
    maskcat_k<<<(B_ * SKV_ + 255) / 256, 256>>>(pmask, smask, mmask, kvm);

    // projections -> bf16 hi/lo (EPI 5). Q: scale 0.25 folded; K/V remap to concat [B,SKV,D].
    gemm_mma<5><<<dim3(16, 16), 256, GEMM_SMEM>>>(qnh, qnl, tWqh, tWql, bq, nullptr, nullptr,
        nullptr, qh, ql, 2048, 2048, 2048, 0.25f, 10, 1024, 0);
    gemm_mma<5><<<dim3(16, 16), 256, GEMM_SMEM>>>(aph, apl, tWkph, tWkpl, bkp, nullptr, nullptr,
        nullptr, kh, kl, 2048, 2048, 1280, 1.f, 10, SKV_, 0);
    gemm_mma<5><<<dim3(16, 16), 256, GEMM_SMEM>>>(aph, apl, tWvph, tWvpl, bvp, nullptr, nullptr,
        nullptr, vh, vl, 2048, 2048, 1280, 1.f, 10, SKV_, 0);
    gemm_mma<5><<<dim3(16, 16), 256, GEMM_SMEM>>>(ash, asl, tWksh, tWksl, bks, nullptr, nullptr,
        nullptr, kh, kl, 2048, 2048, 1024, 1.f, 10, SKV_, SP_);
    gemm_mma<5><<<dim3(16, 16), 256, GEMM_SMEM>>>(ash, asl, tWvsh, tWvsl, bvs, nullptr, nullptr,
        nullptr, vh, vl, 2048, 2048, 1024, 1.f, 10, SKV_, SP_);
    gemm_mma<5><<<dim3(16, 8), 256, GEMM_SMEM>>>(amh, aml, tWkmh, tWkml, bkm, nullptr, nullptr,
        nullptr, kh, kl, 1024, 2048, 768, 1.f, 9, SKV_, SP_ + SS_);
    gemm_mma<5><<<dim3(16, 8), 256, GEMM_SMEM>>>(amh, aml, tWvmh, tWvml, bvm, nullptr, nullptr,
        nullptr, vh, vl, 1024, 2048, 768, 1.f, 9, SKV_, SP_ + SS_);

    // attention (register-resident FA2) -> ctx bf16 hi/lo
    attn_fa2<<<dim3(8, 16, 2), 256, ATTN_SMEM>>>(qh, ql, kh, kl, vh, vl,
                                                 qmask, kvm, cxh, cxl);

    // h = x + tanh(ga)*(ctx@Wo + bo)
    gemm_mma<2><<<dim3(16, 16), 256, GEMM_SMEM>>>(cxh, cxl, tWoh, tWol, bo, x, ga,
        hh, nullptr, nullptr, 2048, 2048, 2048, 1.f, 0, 0, 0);

    // LayerNorm
    layernorm_split<<<B_ * SQ_, 256>>>(hh, lng, lnb, lnh, lnl);

    // FFW
    gemm_mma<3><<<dim3(64, 16), 256, GEMM_SMEM>>>(lnh, lnl, tW1h, tW1l, nullptr, nullptr, nullptr,
        nullptr, ffh, ffl, 2048, INNER_, 2048, 1.f, 0, 0, 0);
    gemm_mma<4><<<dim3(16, 16), 256, GEMM_SMEM>>>(ffh, ffl, tW2h, tW2l, nullptr, hh, gf,
        out, nullptr, nullptr, 2048, 2048, INNER_, 1.f, 0, 0, 0);
}